// round 1
// baseline (speedup 1.0000x reference)
#include <cuda_runtime.h>

#define BB 16384
#define D_SUP 1024
#define D_ANOM 128
#define D_IND 2048
#define D_IN 3200
#define H1 256
#define FEAT 128
#define DEPTH 12
#define NCOND 14
#define CAP 256

// Scratch (device globals; no allocation allowed)
__device__ float g_h1[BB * H1];        // 16 MB
__device__ float g_s0[BB * FEAT];      // 8 MB
__device__ float g_s1[BB * FEAT];      // 8 MB
__device__ float g_Mk[NCOND * FEAT * FEAT];
__device__ float g_aw[BB];

// ---------------------------------------------------------------------------
// aw[b] = mean(|anomaly[b,:]|)   (one warp per row)
// ---------------------------------------------------------------------------
__global__ __launch_bounds__(256) void aw_kernel(const float* __restrict__ anom,
                                                 float* __restrict__ aw) {
    int warp = (blockIdx.x * blockDim.x + threadIdx.x) >> 5;
    int lane = threadIdx.x & 31;
    if (warp >= BB) return;
    float4 v = *(const float4*)(anom + (size_t)warp * D_ANOM + lane * 4);
    float s = fabsf(v.x) + fabsf(v.y) + fabsf(v.z) + fabsf(v.w);
    #pragma unroll
    for (int o = 16; o; o >>= 1) s += __shfl_xor_sync(0xFFFFFFFFu, s, o);
    if (lane == 0) aw[warp] = s * (1.0f / D_ANOM);
}

// ---------------------------------------------------------------------------
// M_k[d][e] = sum_c ref[k][c][d] * obj[k][c][e]   (14 blocks, 256 threads)
// ---------------------------------------------------------------------------
__global__ __launch_bounds__(256) void mk_kernel(const float* __restrict__ refp,
                                                 const float* __restrict__ objp,
                                                 float* __restrict__ Mk) {
    const int k = blockIdx.x;
    __shared__ float Rs[32][FEAT];
    __shared__ float Os[32][FEAT];
    const int tid = threadIdx.x;
    const int tc = tid & 15;   // e-group (8 cols)
    const int tr = tid >> 4;   // d-group (8 rows)
    float acc[8][8] = {};
    const float* rb = refp + (size_t)k * CAP * FEAT;
    const float* ob = objp + (size_t)k * CAP * FEAT;
    for (int c0 = 0; c0 < CAP; c0 += 32) {
        #pragma unroll
        for (int i = tid; i < 32 * FEAT / 4; i += 256) {
            int c = i >> 5, d4 = (i & 31) * 4;
            *(float4*)&Rs[c][d4] = *(const float4*)(rb + (size_t)(c0 + c) * FEAT + d4);
            *(float4*)&Os[c][d4] = *(const float4*)(ob + (size_t)(c0 + c) * FEAT + d4);
        }
        __syncthreads();
        #pragma unroll 8
        for (int c = 0; c < 32; c++) {
            float a[8], b[8];
            #pragma unroll
            for (int i = 0; i < 8; i += 4) *(float4*)&a[i] = *(const float4*)&Rs[c][tr * 8 + i];
            #pragma unroll
            for (int j = 0; j < 8; j += 4) *(float4*)&b[j] = *(const float4*)&Os[c][tc * 8 + j];
            #pragma unroll
            for (int i = 0; i < 8; i++)
                #pragma unroll
                for (int j = 0; j < 8; j++) acc[i][j] += a[i] * b[j];
        }
        __syncthreads();
    }
    float* mb = Mk + (size_t)k * FEAT * FEAT;
    #pragma unroll
    for (int i = 0; i < 8; i++)
        #pragma unroll
        for (int j = 0; j < 8; j += 4) {
            float4 v = make_float4(acc[i][j], acc[i][j + 1], acc[i][j + 2], acc[i][j + 3]);
            *(float4*)(mb + (size_t)(tr * 8 + i) * FEAT + tc * 8 + j) = v;
        }
}

// ---------------------------------------------------------------------------
// Generic SGEMM with bias+ReLU; A may be a column-concat of up to 3 tensors.
// Segment boundaries s1,s2 must be multiples of BK.
// ---------------------------------------------------------------------------
template <int BM, int BN, int BK, int TM, int TN>
__global__ __launch_bounds__((BM / TM) * (BN / TN)) void gemm_bias_relu(
    const float* __restrict__ A0, const float* __restrict__ A1,
    const float* __restrict__ A2, int s1, int s2, int lda0, int lda1, int lda2,
    const float* __restrict__ Bm, const float* __restrict__ bias,
    float* __restrict__ C, int N, int K) {
    constexpr int THREADS = (BM / TM) * (BN / TN);
    __shared__ float As[BK][BM + 4];
    __shared__ float Bs[BK][BN];
    const int tid = threadIdx.x;
    const int tc = tid % (BN / TN);
    const int tr = tid / (BN / TN);
    const int m0 = blockIdx.y * BM;
    const int n0 = blockIdx.x * BN;
    float acc[TM][TN] = {};

    for (int k0 = 0; k0 < K; k0 += BK) {
        const float* Ap;
        int lda, kk0;
        if (k0 < s1)      { Ap = A0; lda = lda0; kk0 = k0; }
        else if (k0 < s2) { Ap = A1; lda = lda1; kk0 = k0 - s1; }
        else              { Ap = A2; lda = lda2; kk0 = k0 - s2; }

        #pragma unroll
        for (int i = tid; i < BM * BK / 4; i += THREADS) {
            int row = i / (BK / 4);
            int kq = (i % (BK / 4)) * 4;
            float4 v = *(const float4*)(Ap + (size_t)(m0 + row) * lda + kk0 + kq);
            As[kq + 0][row] = v.x; As[kq + 1][row] = v.y;
            As[kq + 2][row] = v.z; As[kq + 3][row] = v.w;
        }
        #pragma unroll
        for (int i = tid; i < BK * BN / 4; i += THREADS) {
            int kk = i / (BN / 4);
            int nq = (i % (BN / 4)) * 4;
            *(float4*)&Bs[kk][nq] = *(const float4*)(Bm + (size_t)(k0 + kk) * N + n0 + nq);
        }
        __syncthreads();
        #pragma unroll
        for (int kk = 0; kk < BK; kk++) {
            float a[TM], b[TN];
            #pragma unroll
            for (int i = 0; i < TM; i += 4) *(float4*)&a[i] = *(const float4*)&As[kk][tr * TM + i];
            #pragma unroll
            for (int j = 0; j < TN; j += 4) *(float4*)&b[j] = *(const float4*)&Bs[kk][tc * TN + j];
            #pragma unroll
            for (int i = 0; i < TM; i++)
                #pragma unroll
                for (int j = 0; j < TN; j++) acc[i][j] += a[i] * b[j];
        }
        __syncthreads();
    }
    #pragma unroll
    for (int i = 0; i < TM; i++) {
        int row = m0 + tr * TM + i;
        #pragma unroll
        for (int j = 0; j < TN; j += 4) {
            int col = n0 + tc * TN + j;
            float4 bi = *(const float4*)(bias + col);
            float4 v;
            v.x = fmaxf(acc[i][j + 0] + bi.x, 0.f);
            v.y = fmaxf(acc[i][j + 1] + bi.y, 0.f);
            v.z = fmaxf(acc[i][j + 2] + bi.z, 0.f);
            v.w = fmaxf(acc[i][j + 3] + bi.w, 0.f);
            *(float4*)(C + (size_t)row * N + col) = v;
        }
    }
}

// ---------------------------------------------------------------------------
// Final fused kernel. Block = (k, 64-row tile). Computes
//   G[64 x 256] = m_tile @ [retW_k | M_k]
// cols 0..127 -> retrieved (pre-bias), cols 128..255 -> t = m @ M_k.
// Then w[r] = (t . m)*c + 0.3*aw, out = (retrieved + ret_b)*w.
// ---------------------------------------------------------------------------
__global__ __launch_bounds__(256) void final_kernel(
    const float* __restrict__ state, const float* __restrict__ retW,
    const float* __restrict__ retB, const float* __restrict__ Mk,
    const float* __restrict__ aw, float* __restrict__ out) {
    const int k = blockIdx.x;       // 0..13
    const int b0 = blockIdx.y * 64; // row tile
    __shared__ float As[FEAT][68];  // state^T : As[d][r]
    __shared__ float Bs[8][256];
    __shared__ float wsum[64];
    const int tid = threadIdx.x;
    const int tc = tid & 15;  // 16 cols each
    const int tr = tid >> 4;  // 4 rows each

    if (tid < 64) wsum[tid] = 0.f;
    // load state tile transposed
    #pragma unroll
    for (int i = tid; i < 64 * FEAT / 4; i += 256) {
        int r = i >> 5, d4 = (i & 31) * 4;
        float4 v = *(const float4*)(state + (size_t)(b0 + r) * FEAT + d4);
        As[d4 + 0][r] = v.x; As[d4 + 1][r] = v.y;
        As[d4 + 2][r] = v.z; As[d4 + 3][r] = v.w;
    }

    const float* wb = retW + (size_t)k * FEAT * FEAT;
    const float* mb = Mk + (size_t)k * FEAT * FEAT;
    float acc[4][16] = {};
    for (int k0 = 0; k0 < FEAT; k0 += 8) {
        #pragma unroll
        for (int i = tid; i < 8 * 64; i += 256) {
            int kk = i >> 6;
            int col = (i & 63) * 4;
            const float* src = (col < 128) ? (wb + (size_t)(k0 + kk) * FEAT + col)
                                           : (mb + (size_t)(k0 + kk) * FEAT + (col - 128));
            *(float4*)&Bs[kk][col] = *(const float4*)src;
        }
        __syncthreads();
        #pragma unroll
        for (int kk = 0; kk < 8; kk++) {
            float a[4], b[16];
            *(float4*)&a[0] = *(const float4*)&As[k0 + kk][tr * 4];
            #pragma unroll
            for (int j = 0; j < 16; j += 4) *(float4*)&b[j] = *(const float4*)&Bs[kk][tc * 16 + j];
            #pragma unroll
            for (int i = 0; i < 4; i++)
                #pragma unroll
                for (int j = 0; j < 16; j++) acc[i][j] += a[i] * b[j];
        }
        __syncthreads();
    }

    // quadratic-form reduction: t . m per row
    if (tc >= 8) {
        #pragma unroll
        for (int i = 0; i < 4; i++) {
            int r = tr * 4 + i;
            float p = 0.f;
            #pragma unroll
            for (int j = 0; j < 16; j++) {
                int e = (tc - 8) * 16 + j;
                p += acc[i][j] * As[e][r];
            }
            atomicAdd(&wsum[r], p);
        }
    }
    __syncthreads();
    if (tid < 64) {
        const float cfac = 0.42f * 1.8f / (float)CAP;
        wsum[tid] = wsum[tid] * cfac + 0.3f * aw[b0 + tid];
    }
    __syncthreads();
    if (tc < 8) {
        #pragma unroll
        for (int i = 0; i < 4; i++) {
            int r = tr * 4 + i;
            float w = wsum[r];
            size_t base = (size_t)(b0 + r) * (NCOND * FEAT) + (size_t)k * FEAT + tc * 16;
            #pragma unroll
            for (int j = 0; j < 16; j += 4) {
                float4 bi = *(const float4*)(retB + (size_t)k * FEAT + tc * 16 + j);
                float4 v;
                v.x = (acc[i][j + 0] + bi.x) * w;
                v.y = (acc[i][j + 1] + bi.y) * w;
                v.z = (acc[i][j + 2] + bi.z) * w;
                v.w = (acc[i][j + 3] + bi.w) * w;
                *(float4*)(out + base + j) = v;
            }
        }
    }
}

// ---------------------------------------------------------------------------
extern "C" void kernel_launch(void* const* d_in, const int* in_sizes, int n_in,
                              void* d_out, int out_size) {
    const float* sup  = (const float*)d_in[0];
    const float* anom = (const float*)d_in[1];
    const float* ind  = (const float*)d_in[2];
    const float* ipW1 = (const float*)d_in[3];
    const float* ipb1 = (const float*)d_in[4];
    const float* ipW2 = (const float*)d_in[5];
    const float* ipb2 = (const float*)d_in[6];
    const float* consW = (const float*)d_in[7];
    const float* consB = (const float*)d_in[8];
    const float* refp = (const float*)d_in[9];
    const float* objp = (const float*)d_in[10];
    const float* retW = (const float*)d_in[11];
    const float* retB = (const float*)d_in[12];
    float* out = (float*)d_out;

    float *h1, *s0, *s1, *Mk, *aw;
    cudaGetSymbolAddress((void**)&h1, g_h1);
    cudaGetSymbolAddress((void**)&s0, g_s0);
    cudaGetSymbolAddress((void**)&s1, g_s1);
    cudaGetSymbolAddress((void**)&Mk, g_Mk);
    cudaGetSymbolAddress((void**)&aw, g_aw);

    // independent small preps
    aw_kernel<<<BB * 32 / 256, 256>>>(anom, aw);
    mk_kernel<<<NCOND, 256>>>(refp, objp, Mk);

    // h1 = relu(concat(sup,anom,ind) @ W1 + b1)   [16384,256]
    gemm_bias_relu<128, 128, 16, 8, 8><<<dim3(H1 / 128, BB / 128), 256>>>(
        sup, anom, ind, D_SUP, D_SUP + D_ANOM, D_SUP, D_ANOM, D_IND,
        ipW1, ipb1, h1, H1, D_IN);

    // s0 = relu(h1 @ W2 + b2)   [16384,128]
    gemm_bias_relu<64, 128, 16, 4, 8><<<dim3(1, BB / 64), 256>>>(
        h1, h1, h1, H1, H1, H1, H1, H1, ipW2, ipb2, s0, FEAT, H1);

    // 12 consolidator layers, ping-pong s0 <-> s1
    for (int l = 0; l < DEPTH; l++) {
        const float* in = (l & 1) ? s1 : s0;
        float* o = (l & 1) ? s0 : s1;
        gemm_bias_relu<64, 128, 16, 4, 8><<<dim3(1, BB / 64), 256>>>(
            in, in, in, FEAT, FEAT, FEAT, FEAT, FEAT,
            consW + (size_t)l * FEAT * FEAT, consB + (size_t)l * FEAT, o, FEAT, FEAT);
    }
    const float* sfin = (DEPTH & 1) ? s1 : s0;  // DEPTH=12 even -> s0

    // final fused retrieval + interference weighting
    final_kernel<<<dim3(NCOND, BB / 64), 256>>>(sfin, retW, retB, Mk, aw, out);
}

// round 3
// speedup vs baseline: 1.2929x; 1.2929x over previous
#include <cuda_runtime.h>
#include <cuda_bf16.h>
#include <stdint.h>

#define BB 16384
#define D_SUP 1024
#define D_ANOM 128
#define D_IND 2048
#define D_IN 3200
#define H1 256
#define FEAT 128
#define DEPTH 12
#define NCOND 14
#define CAP 256

// ---------------- scratch (device globals; no allocation allowed) ----------
__device__ __nv_bfloat16 g_Wh1[H1 * D_IN];           // W1^T hi [256][3200]
__device__ __nv_bfloat16 g_Wl1[H1 * D_IN];
__device__ __nv_bfloat16 g_Wh2[FEAT * H1];           // W2^T hi [128][256]
__device__ __nv_bfloat16 g_Wl2[FEAT * H1];
__device__ __nv_bfloat16 g_WhC[DEPTH * FEAT * FEAT]; // consW^T hi [12][128][128]
__device__ __nv_bfloat16 g_WlC[DEPTH * FEAT * FEAT];
__device__ __nv_bfloat16 g_h1h[BB * H1];             // h1 hi/lo [16384][256]
__device__ __nv_bfloat16 g_h1l[BB * H1];
__device__ __nv_bfloat16 g_sh0[BB * FEAT];
__device__ __nv_bfloat16 g_sl0[BB * FEAT];
__device__ __nv_bfloat16 g_sh1[BB * FEAT];
__device__ __nv_bfloat16 g_sl1[BB * FEAT];
__device__ float g_sf[BB * FEAT];                    // final state fp32
__device__ float g_Mk[NCOND * FEAT * FEAT];
__device__ float g_aw[BB];

// ---------------- helpers --------------------------------------------------
__device__ __forceinline__ uint32_t smem_u32(const void* p) {
    uint32_t a;
    asm("{ .reg .u64 t; cvta.to.shared.u64 t, %1; cvt.u32.u64 %0, t; }" : "=r"(a) : "l"(p));
    return a;
}
__device__ __forceinline__ void ldsm4(uint32_t* r, uint32_t addr) {
    asm volatile("ldmatrix.sync.aligned.m8n8.x4.shared.b16 {%0,%1,%2,%3}, [%4];"
                 : "=r"(r[0]), "=r"(r[1]), "=r"(r[2]), "=r"(r[3]) : "r"(addr));
}
__device__ __forceinline__ void mma_bf16(float* c, const uint32_t* a, const uint32_t* b) {
    asm volatile("mma.sync.aligned.m16n8k16.row.col.f32.bf16.bf16.f32 "
                 "{%0,%1,%2,%3}, {%4,%5,%6,%7}, {%8,%9}, {%0,%1,%2,%3};"
                 : "+f"(c[0]), "+f"(c[1]), "+f"(c[2]), "+f"(c[3])
                 : "r"(a[0]), "r"(a[1]), "r"(a[2]), "r"(a[3]), "r"(b[0]), "r"(b[1]));
}

// ---------------- aw[b] = mean(|anomaly[b,:]|) -----------------------------
__global__ __launch_bounds__(256) void aw_kernel(const float* __restrict__ anom,
                                                 float* __restrict__ aw) {
    int warp = (blockIdx.x * blockDim.x + threadIdx.x) >> 5;
    int lane = threadIdx.x & 31;
    if (warp >= BB) return;
    float4 v = *(const float4*)(anom + (size_t)warp * D_ANOM + lane * 4);
    float s = fabsf(v.x) + fabsf(v.y) + fabsf(v.z) + fabsf(v.w);
    #pragma unroll
    for (int o = 16; o; o >>= 1) s += __shfl_xor_sync(0xFFFFFFFFu, s, o);
    if (lane == 0) aw[warp] = s * (1.0f / D_ANOM);
}

// ---------------- M_k = R_k^T O_k ------------------------------------------
__global__ __launch_bounds__(256) void mk_kernel(const float* __restrict__ refp,
                                                 const float* __restrict__ objp,
                                                 float* __restrict__ Mk) {
    const int k = blockIdx.x;
    __shared__ float Rs[32][FEAT];
    __shared__ float Os[32][FEAT];
    const int tid = threadIdx.x;
    const int tc = tid & 15;
    const int tr = tid >> 4;
    float acc[8][8] = {};
    const float* rb = refp + (size_t)k * CAP * FEAT;
    const float* ob = objp + (size_t)k * CAP * FEAT;
    for (int c0 = 0; c0 < CAP; c0 += 32) {
        #pragma unroll
        for (int i = tid; i < 32 * FEAT / 4; i += 256) {
            int c = i >> 5, d4 = (i & 31) * 4;
            *(float4*)&Rs[c][d4] = *(const float4*)(rb + (size_t)(c0 + c) * FEAT + d4);
            *(float4*)&Os[c][d4] = *(const float4*)(ob + (size_t)(c0 + c) * FEAT + d4);
        }
        __syncthreads();
        #pragma unroll 8
        for (int c = 0; c < 32; c++) {
            float a[8], b[8];
            #pragma unroll
            for (int i = 0; i < 8; i += 4) *(float4*)&a[i] = *(const float4*)&Rs[c][tr * 8 + i];
            #pragma unroll
            for (int j = 0; j < 8; j += 4) *(float4*)&b[j] = *(const float4*)&Os[c][tc * 8 + j];
            #pragma unroll
            for (int i = 0; i < 8; i++)
                #pragma unroll
                for (int j = 0; j < 8; j++) acc[i][j] += a[i] * b[j];
        }
        __syncthreads();
    }
    float* mb = Mk + (size_t)k * FEAT * FEAT;
    #pragma unroll
    for (int i = 0; i < 8; i++)
        #pragma unroll
        for (int j = 0; j < 8; j += 4) {
            float4 v = make_float4(acc[i][j], acc[i][j + 1], acc[i][j + 2], acc[i][j + 3]);
            *(float4*)(mb + (size_t)(tr * 8 + i) * FEAT + tc * 8 + j) = v;
        }
}

// ---------------- transpose + hi/lo split:  Wt[n][k] = W[k][n] -------------
__global__ __launch_bounds__(256) void tsplit_kernel(const float* __restrict__ W,
                                                     __nv_bfloat16* __restrict__ Wh,
                                                     __nv_bfloat16* __restrict__ Wl,
                                                     int K, int N) {
    const int batch = blockIdx.z;
    W += (size_t)batch * K * N;
    Wh += (size_t)batch * N * K;
    Wl += (size_t)batch * N * K;
    __shared__ float t[32][33];
    const int k0 = blockIdx.x * 32;
    const int n0 = blockIdx.y * 32;
    const int tx = threadIdx.x, ty = threadIdx.y;
    #pragma unroll
    for (int i = 0; i < 4; i++)
        t[ty + 8 * i][tx] = W[(size_t)(k0 + ty + 8 * i) * N + n0 + tx];
    __syncthreads();
    #pragma unroll
    for (int i = 0; i < 4; i++) {
        int n = n0 + ty + 8 * i;
        int k = k0 + tx;
        float v = t[tx][ty + 8 * i];
        __nv_bfloat16 hi = __float2bfloat16(v);
        __nv_bfloat16 lo = __float2bfloat16(v - __bfloat162float(hi));
        Wh[(size_t)n * K + k] = hi;
        Wl[(size_t)n * K + k] = lo;
    }
}

// ===========================================================================
// Unified HMMA GEMM: out = relu( A @ W^T + bias )
//   A: fp32 (3-segment concat) if INF32, else bf16 hi/lo pair (row stride K)
//   W: bf16 hi/lo pair, [N][K] K-major
//   out: fp32, or bf16 hi/lo pair (row stride = gridDim.x * BN)
//   3-pass split: Ah*Wh + Ah*Wl + Al*Wh
// ===========================================================================
template <int BM, int BN, int THREADS, bool INF32, bool OUTF32>
__global__ __launch_bounds__(THREADS, 1) void mma_gemm(
    const float* __restrict__ A0, const float* __restrict__ A1,
    const float* __restrict__ A2,
    const __nv_bfloat16* __restrict__ Ah, const __nv_bfloat16* __restrict__ Al,
    const __nv_bfloat16* __restrict__ Bh, const __nv_bfloat16* __restrict__ Bl,
    const float* __restrict__ bias,
    float* __restrict__ Of, __nv_bfloat16* __restrict__ Oh,
    __nv_bfloat16* __restrict__ Ol, int K) {
    constexpr int LDS = 40;                 // halves per smem row (stride 80B, 5x16B)
    constexpr int NW = THREADS / 32;
    constexpr int WN = BN / 64;             // warps along N (warp tile 32x64)
    constexpr int WM = NW / WN;             // warps along M
    static_assert(WM * 32 == BM, "warp M tiling");

    extern __shared__ __nv_bfloat16 smp[];
    __nv_bfloat16* sAh = smp;
    __nv_bfloat16* sAl = sAh + BM * LDS;
    __nv_bfloat16* sBh = sAl + BM * LDS;
    __nv_bfloat16* sBl = sBh + BN * LDS;

    const int tid = threadIdx.x;
    const int wid = tid >> 5, lane = tid & 31;
    const int warpM = (wid % WM) * 32;
    const int warpN = (wid / WM) * 64;
    const int m0 = blockIdx.y * BM;
    const int n0 = blockIdx.x * BN;
    const int Nout = gridDim.x * BN;

    const uint32_t aAh = smem_u32(sAh), aAl = smem_u32(sAl);
    const uint32_t aBh = smem_u32(sBh), aBl = smem_u32(sBl);

    float acc[2][8][4];
    #pragma unroll
    for (int i = 0; i < 2; i++)
        #pragma unroll
        for (int j = 0; j < 8; j++)
            #pragma unroll
            for (int q = 0; q < 4; q++) acc[i][j][q] = 0.f;

    for (int k0 = 0; k0 < K; k0 += 32) {
        __syncthreads();
        if (INF32) {
            const float* Ap; int lda, kk;
            if (k0 < D_SUP)               { Ap = A0; lda = D_SUP;  kk = k0; }
            else if (k0 < D_SUP + D_ANOM) { Ap = A1; lda = D_ANOM; kk = k0 - D_SUP; }
            else                          { Ap = A2; lda = D_IND;  kk = k0 - D_SUP - D_ANOM; }
            #pragma unroll
            for (int t = 0; t < BM * 8 / THREADS; t++) {
                int idx = tid + t * THREADS;       // BM*8 float4 chunks
                int row = idx >> 3, q = idx & 7;
                float4 v = *(const float4*)(Ap + (size_t)(m0 + row) * lda + kk + q * 4);
                __nv_bfloat16 hx = __float2bfloat16(v.x), hy = __float2bfloat16(v.y);
                __nv_bfloat16 hz = __float2bfloat16(v.z), hw = __float2bfloat16(v.w);
                __nv_bfloat162 h01 = {hx, hy}, h23 = {hz, hw};
                __nv_bfloat162 l01 = __floats2bfloat162_rn(v.x - __bfloat162float(hx),
                                                           v.y - __bfloat162float(hy));
                __nv_bfloat162 l23 = __floats2bfloat162_rn(v.z - __bfloat162float(hz),
                                                           v.w - __bfloat162float(hw));
                int off = row * LDS + q * 4;
                *(__nv_bfloat162*)(sAh + off) = h01;
                *(__nv_bfloat162*)(sAh + off + 2) = h23;
                *(__nv_bfloat162*)(sAl + off) = l01;
                *(__nv_bfloat162*)(sAl + off + 2) = l23;
            }
        } else {
            #pragma unroll
            for (int t = 0; t < BM * 8 / THREADS; t++) {
                int idx = tid + t * THREADS;       // per array BM*4 uint4
                int half = idx >= BM * 4;
                int cc = half ? idx - BM * 4 : idx;
                int row = cc >> 2, q = cc & 3;
                const __nv_bfloat16* src = (half ? Al : Ah) + (size_t)(m0 + row) * K + k0 + q * 8;
                *(uint4*)((half ? sAl : sAh) + row * LDS + q * 8) = *(const uint4*)src;
            }
        }
        #pragma unroll
        for (int t = 0; t < BN * 8 / THREADS; t++) {
            int idx = tid + t * THREADS;           // per array BN*4 uint4
            int half = idx >= BN * 4;
            int cc = half ? idx - BN * 4 : idx;
            int row = cc >> 2, q = cc & 3;
            const __nv_bfloat16* src = (half ? Bl : Bh) + (size_t)(n0 + row) * K + k0 + q * 8;
            *(uint4*)((half ? sBl : sBh) + row * LDS + q * 8) = *(const uint4*)src;
        }
        __syncthreads();

        #pragma unroll
        for (int kq = 0; kq < 2; kq++) {
            uint32_t a_h[2][4], a_l[2][4], bfr[8][2];
            const int colh = kq * 16 + ((lane >> 4) << 3);
            #pragma unroll
            for (int mt = 0; mt < 2; mt++) {
                int row = warpM + mt * 16 + (lane & 15);
                ldsm4(a_h[mt], aAh + (uint32_t)(row * LDS + colh) * 2);
                ldsm4(a_l[mt], aAl + (uint32_t)(row * LDS + colh) * 2);
            }
            #pragma unroll
            for (int nt2 = 0; nt2 < 4; nt2++) {
                int row = warpN + nt2 * 16 + (lane & 15);
                uint32_t r[4];
                ldsm4(r, aBh + (uint32_t)(row * LDS + colh) * 2);
                bfr[2 * nt2][0] = r[0]; bfr[2 * nt2][1] = r[2];
                bfr[2 * nt2 + 1][0] = r[1]; bfr[2 * nt2 + 1][1] = r[3];
            }
            #pragma unroll
            for (int mt = 0; mt < 2; mt++)
                #pragma unroll
                for (int nt = 0; nt < 8; nt++) mma_bf16(acc[mt][nt], a_h[mt], bfr[nt]);
            #pragma unroll
            for (int mt = 0; mt < 2; mt++)
                #pragma unroll
                for (int nt = 0; nt < 8; nt++) mma_bf16(acc[mt][nt], a_l[mt], bfr[nt]);
            #pragma unroll
            for (int nt2 = 0; nt2 < 4; nt2++) {
                int row = warpN + nt2 * 16 + (lane & 15);
                uint32_t r[4];
                ldsm4(r, aBl + (uint32_t)(row * LDS + colh) * 2);
                bfr[2 * nt2][0] = r[0]; bfr[2 * nt2][1] = r[2];
                bfr[2 * nt2 + 1][0] = r[1]; bfr[2 * nt2 + 1][1] = r[3];
            }
            #pragma unroll
            for (int mt = 0; mt < 2; mt++)
                #pragma unroll
                for (int nt = 0; nt < 8; nt++) mma_bf16(acc[mt][nt], a_h[mt], bfr[nt]);
        }
    }

    // ---- epilogue: bias + relu, write fp32 or bf16 hi/lo pair ----
    #pragma unroll
    for (int mt = 0; mt < 2; mt++) {
        const int r0 = m0 + warpM + mt * 16 + (lane >> 2);
        #pragma unroll
        for (int nt = 0; nt < 8; nt++) {
            const int cc = n0 + warpN + nt * 8 + ((lane & 3) << 1);
            float2 bv = *(const float2*)(bias + cc);
            float v00 = fmaxf(acc[mt][nt][0] + bv.x, 0.f);
            float v01 = fmaxf(acc[mt][nt][1] + bv.y, 0.f);
            float v10 = fmaxf(acc[mt][nt][2] + bv.x, 0.f);
            float v11 = fmaxf(acc[mt][nt][3] + bv.y, 0.f);
            if (OUTF32) {
                *(float2*)(Of + (size_t)r0 * Nout + cc) = make_float2(v00, v01);
                *(float2*)(Of + (size_t)(r0 + 8) * Nout + cc) = make_float2(v10, v11);
            } else {
                __nv_bfloat16 h00 = __float2bfloat16(v00), h01 = __float2bfloat16(v01);
                __nv_bfloat16 h10 = __float2bfloat16(v10), h11 = __float2bfloat16(v11);
                __nv_bfloat162 hi0 = {h00, h01}, hi1 = {h10, h11};
                __nv_bfloat162 lo0 = __floats2bfloat162_rn(v00 - __bfloat162float(h00),
                                                           v01 - __bfloat162float(h01));
                __nv_bfloat162 lo1 = __floats2bfloat162_rn(v10 - __bfloat162float(h10),
                                                           v11 - __bfloat162float(h11));
                *(__nv_bfloat162*)(Oh + (size_t)r0 * Nout + cc) = hi0;
                *(__nv_bfloat162*)(Ol + (size_t)r0 * Nout + cc) = lo0;
                *(__nv_bfloat162*)(Oh + (size_t)(r0 + 8) * Nout + cc) = hi1;
                *(__nv_bfloat162*)(Ol + (size_t)(r0 + 8) * Nout + cc) = lo1;
            }
        }
    }
}

// ---------------- final fused retrieval + interference weighting -----------
__global__ __launch_bounds__(256) void final_kernel(
    const float* __restrict__ state, const float* __restrict__ retW,
    const float* __restrict__ retB, const float* __restrict__ Mk,
    const float* __restrict__ aw, float* __restrict__ out) {
    const int k = blockIdx.x;
    const int b0 = blockIdx.y * 64;
    __shared__ float As[FEAT][68];
    __shared__ float Bs[8][256];
    __shared__ float wsum[64];
    const int tid = threadIdx.x;
    const int tc = tid & 15;
    const int tr = tid >> 4;

    if (tid < 64) wsum[tid] = 0.f;
    #pragma unroll
    for (int i = tid; i < 64 * FEAT / 4; i += 256) {
        int r = i >> 5, d4 = (i & 31) * 4;
        float4 v = *(const float4*)(state + (size_t)(b0 + r) * FEAT + d4);
        As[d4 + 0][r] = v.x; As[d4 + 1][r] = v.y;
        As[d4 + 2][r] = v.z; As[d4 + 3][r] = v.w;
    }

    const float* wb = retW + (size_t)k * FEAT * FEAT;
    const float* mb = Mk + (size_t)k * FEAT * FEAT;
    float acc[4][16] = {};
    for (int k0 = 0; k0 < FEAT; k0 += 8) {
        #pragma unroll
        for (int i = tid; i < 8 * 64; i += 256) {
            int kk = i >> 6;
            int col = (i & 63) * 4;
            const float* src = (col < 128) ? (wb + (size_t)(k0 + kk) * FEAT + col)
                                           : (mb + (size_t)(k0 + kk) * FEAT + (col - 128));
            *(float4*)&Bs[kk][col] = *(const float4*)src;
        }
        __syncthreads();
        #pragma unroll
        for (int kk = 0; kk < 8; kk++) {
            float a[4], b[16];
            *(float4*)&a[0] = *(const float4*)&As[k0 + kk][tr * 4];
            #pragma unroll
            for (int j = 0; j < 16; j += 4) *(float4*)&b[j] = *(const float4*)&Bs[kk][tc * 16 + j];
            #pragma unroll
            for (int i = 0; i < 4; i++)
                #pragma unroll
                for (int j = 0; j < 16; j++) acc[i][j] += a[i] * b[j];
        }
        __syncthreads();
    }

    if (tc >= 8) {
        #pragma unroll
        for (int i = 0; i < 4; i++) {
            int r = tr * 4 + i;
            float p = 0.f;
            #pragma unroll
            for (int j = 0; j < 16; j++) {
                int e = (tc - 8) * 16 + j;
                p += acc[i][j] * As[e][r];
            }
            atomicAdd(&wsum[r], p);
        }
    }
    __syncthreads();
    if (tid < 64) {
        const float cfac = 0.42f * 1.8f / (float)CAP;
        wsum[tid] = wsum[tid] * cfac + 0.3f * aw[b0 + tid];
    }
    __syncthreads();
    if (tc < 8) {
        #pragma unroll
        for (int i = 0; i < 4; i++) {
            int r = tr * 4 + i;
            float w = wsum[r];
            size_t base = (size_t)(b0 + r) * (NCOND * FEAT) + (size_t)k * FEAT + tc * 16;
            #pragma unroll
            for (int j = 0; j < 16; j += 4) {
                float4 bi = *(const float4*)(retB + (size_t)k * FEAT + tc * 16 + j);
                float4 v;
                v.x = (acc[i][j + 0] + bi.x) * w;
                v.y = (acc[i][j + 1] + bi.y) * w;
                v.z = (acc[i][j + 2] + bi.z) * w;
                v.w = (acc[i][j + 3] + bi.w) * w;
                *(float4*)(out + base + j) = v;
            }
        }
    }
}

// ===========================================================================
extern "C" void kernel_launch(void* const* d_in, const int* in_sizes, int n_in,
                              void* d_out, int out_size) {
    const float* sup  = (const float*)d_in[0];
    const float* anom = (const float*)d_in[1];
    const float* ind  = (const float*)d_in[2];
    const float* ipW1 = (const float*)d_in[3];
    const float* ipb1 = (const float*)d_in[4];
    const float* ipW2 = (const float*)d_in[5];
    const float* ipb2 = (const float*)d_in[6];
    const float* consW = (const float*)d_in[7];
    const float* consB = (const float*)d_in[8];
    const float* refp = (const float*)d_in[9];
    const float* objp = (const float*)d_in[10];
    const float* retW = (const float*)d_in[11];
    const float* retB = (const float*)d_in[12];
    float* out = (float*)d_out;

    __nv_bfloat16 *Wh1, *Wl1, *Wh2, *Wl2, *WhC, *WlC;
    __nv_bfloat16 *h1h, *h1l, *sh0, *sl0, *sh1, *sl1;
    float *sf, *Mk, *aw;
    cudaGetSymbolAddress((void**)&Wh1, g_Wh1);
    cudaGetSymbolAddress((void**)&Wl1, g_Wl1);
    cudaGetSymbolAddress((void**)&Wh2, g_Wh2);
    cudaGetSymbolAddress((void**)&Wl2, g_Wl2);
    cudaGetSymbolAddress((void**)&WhC, g_WhC);
    cudaGetSymbolAddress((void**)&WlC, g_WlC);
    cudaGetSymbolAddress((void**)&h1h, g_h1h);
    cudaGetSymbolAddress((void**)&h1l, g_h1l);
    cudaGetSymbolAddress((void**)&sh0, g_sh0);
    cudaGetSymbolAddress((void**)&sl0, g_sl0);
    cudaGetSymbolAddress((void**)&sh1, g_sh1);
    cudaGetSymbolAddress((void**)&sl1, g_sl1);
    cudaGetSymbolAddress((void**)&sf, g_sf);
    cudaGetSymbolAddress((void**)&Mk, g_Mk);
    cudaGetSymbolAddress((void**)&aw, g_aw);

    const int SM_G1 = (128 + 256) * 40 * 2 * 2;  // 61440
    const int SM_LY = (128 + 128) * 40 * 2 * 2;  // 40960
    cudaFuncSetAttribute(mma_gemm<128, 256, 512, true, false>,
                         cudaFuncAttributeMaxDynamicSharedMemorySize, SM_G1);

    // preps
    aw_kernel<<<BB * 32 / 256, 256>>>(anom, aw);
    mk_kernel<<<NCOND, 256>>>(refp, objp, Mk);
    tsplit_kernel<<<dim3(D_IN / 32, H1 / 32, 1), dim3(32, 8)>>>(ipW1, Wh1, Wl1, D_IN, H1);
    tsplit_kernel<<<dim3(H1 / 32, FEAT / 32, 1), dim3(32, 8)>>>(ipW2, Wh2, Wl2, H1, FEAT);
    tsplit_kernel<<<dim3(FEAT / 32, FEAT / 32, DEPTH), dim3(32, 8)>>>(consW, WhC, WlC, FEAT, FEAT);

    // GEMM1: h1 = relu(concat @ W1 + b1) -> bf16 hi/lo
    mma_gemm<128, 256, 512, true, false><<<dim3(1, BB / 128), 512, SM_G1>>>(
        sup, anom, ind, nullptr, nullptr, Wh1, Wl1, ipb1, nullptr, h1h, h1l, D_IN);

    // GEMM2: s0 = relu(h1 @ W2 + b2) -> bf16 hi/lo
    mma_gemm<128, 128, 256, false, false><<<dim3(1, BB / 128), 256, SM_LY>>>(
        nullptr, nullptr, nullptr, h1h, h1l, Wh2, Wl2, ipb2, nullptr, sh0, sl0, H1);

    // consolidator layers 0..10 (bf16 pair -> bf16 pair), ping-pong
    for (int l = 0; l < DEPTH - 1; l++) {
        const __nv_bfloat16* ih = (l & 1) ? sh1 : sh0;
        const __nv_bfloat16* il = (l & 1) ? sl1 : sl0;
        __nv_bfloat16* oh = (l & 1) ? sh0 : sh1;
        __nv_bfloat16* ol = (l & 1) ? sl0 : sl1;
        mma_gemm<128, 128, 256, false, false><<<dim3(1, BB / 128), 256, SM_LY>>>(
            nullptr, nullptr, nullptr, ih, il,
            WhC + (size_t)l * FEAT * FEAT, WlC + (size_t)l * FEAT * FEAT,
            consB + (size_t)l * FEAT, nullptr, oh, ol, FEAT);
    }
    // layer 11 -> fp32 state (input of layer 11 is s1: l=10 is even, wrote sh1)
    mma_gemm<128, 128, 256, false, true><<<dim3(1, BB / 128), 256, SM_LY>>>(
        nullptr, nullptr, nullptr, sh1, sl1,
        WhC + (size_t)(DEPTH - 1) * FEAT * FEAT, WlC + (size_t)(DEPTH - 1) * FEAT * FEAT,
        consB + (size_t)(DEPTH - 1) * FEAT, sf, nullptr, nullptr, FEAT);

    // final fused retrieval + interference weighting
    final_kernel<<<dim3(NCOND, BB / 64), 256>>>(sf, retW, retB, Mk, aw, out);
}

// round 4
// speedup vs baseline: 3.0184x; 2.3347x over previous
#include <cuda_runtime.h>
#include <cuda_bf16.h>
#include <stdint.h>

#define BB 16384
#define D_SUP 1024
#define D_ANOM 128
#define D_IND 2048
#define D_IN 3200
#define H1 256
#define FEAT 128
#define DEPTH 12
#define NCOND 14
#define CAP 256

// ---------------- scratch (device globals; no allocation allowed) ----------
__device__ __nv_bfloat16 g_Wh1[H1 * D_IN];           // W1^T hi [256][3200]
__device__ __nv_bfloat16 g_Wl1[H1 * D_IN];
__device__ __nv_bfloat16 g_Wh2[FEAT * H1];           // W2^T hi [128][256]
__device__ __nv_bfloat16 g_Wl2[FEAT * H1];
__device__ __nv_bfloat16 g_WhC[DEPTH * FEAT * FEAT]; // consW^T hi [12][128][128]
__device__ __nv_bfloat16 g_WlC[DEPTH * FEAT * FEAT];
__device__ __nv_bfloat16 g_h1h[BB * H1];             // h1 hi/lo [16384][256]
__device__ __nv_bfloat16 g_h1l[BB * H1];
__device__ __nv_bfloat16 g_WfinH[NCOND * 256 * FEAT]; // [k][256][128]: rows 0-127 retW^T, 128-255 Mk^T
__device__ __nv_bfloat16 g_WfinL[NCOND * 256 * FEAT];
__device__ float g_aw[BB];

// ---------------- helpers --------------------------------------------------
__device__ __forceinline__ uint32_t smem_u32(const void* p) {
    uint32_t a;
    asm("{ .reg .u64 t; cvta.to.shared.u64 t, %1; cvt.u32.u64 %0, t; }" : "=r"(a) : "l"(p));
    return a;
}
__device__ __forceinline__ void ldsm4(uint32_t* r, uint32_t addr) {
    asm volatile("ldmatrix.sync.aligned.m8n8.x4.shared.b16 {%0,%1,%2,%3}, [%4];"
                 : "=r"(r[0]), "=r"(r[1]), "=r"(r[2]), "=r"(r[3]) : "r"(addr));
}
__device__ __forceinline__ void mma_bf16(float* c, const uint32_t* a, const uint32_t* b) {
    asm volatile("mma.sync.aligned.m16n8k16.row.col.f32.bf16.bf16.f32 "
                 "{%0,%1,%2,%3}, {%4,%5,%6,%7}, {%8,%9}, {%0,%1,%2,%3};"
                 : "+f"(c[0]), "+f"(c[1]), "+f"(c[2]), "+f"(c[3])
                 : "r"(a[0]), "r"(a[1]), "r"(a[2]), "r"(a[3]), "r"(b[0]), "r"(b[1]));
}

// ---------------- aw[b] = mean(|anomaly[b,:]|) -----------------------------
__global__ __launch_bounds__(256) void aw_kernel(const float* __restrict__ anom,
                                                 float* __restrict__ aw) {
    int warp = (blockIdx.x * blockDim.x + threadIdx.x) >> 5;
    int lane = threadIdx.x & 31;
    if (warp >= BB) return;
    float4 v = *(const float4*)(anom + (size_t)warp * D_ANOM + lane * 4);
    float s = fabsf(v.x) + fabsf(v.y) + fabsf(v.z) + fabsf(v.w);
    #pragma unroll
    for (int o = 16; o; o >>= 1) s += __shfl_xor_sync(0xFFFFFFFFu, s, o);
    if (lane == 0) aw[warp] = s * (1.0f / D_ANOM);
}

// ---------------- Mk^T hi/lo into Wfin rows 128-255 ------------------------
__global__ __launch_bounds__(256) void mkfin_kernel(const float* __restrict__ refp,
                                                    const float* __restrict__ objp,
                                                    __nv_bfloat16* __restrict__ WfH,
                                                    __nv_bfloat16* __restrict__ WfL) {
    const int k = blockIdx.x;
    __shared__ float Rs[32][FEAT];
    __shared__ float Os[32][FEAT];
    const int tid = threadIdx.x;
    const int tc = tid & 15;   // e group
    const int tr = tid >> 4;   // d group
    float acc[8][8] = {};
    const float* rb = refp + (size_t)k * CAP * FEAT;
    const float* ob = objp + (size_t)k * CAP * FEAT;
    for (int c0 = 0; c0 < CAP; c0 += 32) {
        #pragma unroll
        for (int i = tid; i < 32 * FEAT / 4; i += 256) {
            int c = i >> 5, d4 = (i & 31) * 4;
            *(float4*)&Rs[c][d4] = *(const float4*)(rb + (size_t)(c0 + c) * FEAT + d4);
            *(float4*)&Os[c][d4] = *(const float4*)(ob + (size_t)(c0 + c) * FEAT + d4);
        }
        __syncthreads();
        #pragma unroll 8
        for (int c = 0; c < 32; c++) {
            float a[8], b[8];
            #pragma unroll
            for (int i = 0; i < 8; i += 4) *(float4*)&a[i] = *(const float4*)&Rs[c][tr * 8 + i];
            #pragma unroll
            for (int j = 0; j < 8; j += 4) *(float4*)&b[j] = *(const float4*)&Os[c][tc * 8 + j];
            #pragma unroll
            for (int i = 0; i < 8; i++)
                #pragma unroll
                for (int j = 0; j < 8; j++) acc[i][j] += a[i] * b[j];
        }
        __syncthreads();
    }
    // acc[i][j] = Mk[d=tr*8+i][e=tc*8+j]; write Mk^T: Wfin[(128+e)][d]
    #pragma unroll
    for (int j = 0; j < 8; j++) {
        int e = tc * 8 + j;
        __nv_bfloat16 hv[8], lv[8];
        #pragma unroll
        for (int i = 0; i < 8; i++) {
            float v = acc[i][j];
            __nv_bfloat16 hi = __float2bfloat16(v);
            hv[i] = hi;
            lv[i] = __float2bfloat16(v - __bfloat162float(hi));
        }
        size_t base = (size_t)k * 256 * FEAT + (size_t)(128 + e) * FEAT + tr * 8;
        *(uint4*)(WfH + base) = *(uint4*)hv;
        *(uint4*)(WfL + base) = *(uint4*)lv;
    }
}

// ---------------- transpose + hi/lo split:  dst[n][k] = W[k][n] ------------
__global__ __launch_bounds__(256) void tsplit_kernel(const float* __restrict__ W,
                                                     __nv_bfloat16* __restrict__ Wh,
                                                     __nv_bfloat16* __restrict__ Wl,
                                                     int K, int N, int dstBatchStride) {
    const int batch = blockIdx.z;
    W += (size_t)batch * K * N;
    Wh += (size_t)batch * dstBatchStride;
    Wl += (size_t)batch * dstBatchStride;
    __shared__ float t[32][33];
    const int k0 = blockIdx.x * 32;
    const int n0 = blockIdx.y * 32;
    const int tx = threadIdx.x, ty = threadIdx.y;
    #pragma unroll
    for (int i = 0; i < 4; i++)
        t[ty + 8 * i][tx] = W[(size_t)(k0 + ty + 8 * i) * N + n0 + tx];
    __syncthreads();
    #pragma unroll
    for (int i = 0; i < 4; i++) {
        int n = n0 + ty + 8 * i;
        int k = k0 + tx;
        float v = t[tx][ty + 8 * i];
        __nv_bfloat16 hi = __float2bfloat16(v);
        __nv_bfloat16 lo = __float2bfloat16(v - __bfloat162float(hi));
        Wh[(size_t)n * K + k] = hi;
        Wl[(size_t)n * K + k] = lo;
    }
}

// ===========================================================================
// GEMM1 on HMMA (unchanged from R3): h1 = relu(concat @ W1 + b1) -> bf16 pair
// ===========================================================================
template <int BM, int BN, int THREADS>
__global__ __launch_bounds__(THREADS, 1) void mma_gemm1(
    const float* __restrict__ A0, const float* __restrict__ A1,
    const float* __restrict__ A2,
    const __nv_bfloat16* __restrict__ Bh, const __nv_bfloat16* __restrict__ Bl,
    const float* __restrict__ bias,
    __nv_bfloat16* __restrict__ Oh, __nv_bfloat16* __restrict__ Ol, int K) {
    constexpr int LDS = 40;
    constexpr int NW = THREADS / 32;
    constexpr int WN = BN / 64;
    constexpr int WM = NW / WN;
    static_assert(WM * 32 == BM, "warp M tiling");

    extern __shared__ __nv_bfloat16 smp[];
    __nv_bfloat16* sAh = smp;
    __nv_bfloat16* sAl = sAh + BM * LDS;
    __nv_bfloat16* sBh = sAl + BM * LDS;
    __nv_bfloat16* sBl = sBh + BN * LDS;

    const int tid = threadIdx.x;
    const int wid = tid >> 5, lane = tid & 31;
    const int warpM = (wid % WM) * 32;
    const int warpN = (wid / WM) * 64;
    const int m0 = blockIdx.y * BM;
    const int n0 = blockIdx.x * BN;
    const int Nout = gridDim.x * BN;

    const uint32_t aAh = smem_u32(sAh), aAl = smem_u32(sAl);
    const uint32_t aBh = smem_u32(sBh), aBl = smem_u32(sBl);

    float acc[2][8][4];
    #pragma unroll
    for (int i = 0; i < 2; i++)
        #pragma unroll
        for (int j = 0; j < 8; j++)
            #pragma unroll
            for (int q = 0; q < 4; q++) acc[i][j][q] = 0.f;

    for (int k0 = 0; k0 < K; k0 += 32) {
        __syncthreads();
        {
            const float* Ap; int lda, kk;
            if (k0 < D_SUP)               { Ap = A0; lda = D_SUP;  kk = k0; }
            else if (k0 < D_SUP + D_ANOM) { Ap = A1; lda = D_ANOM; kk = k0 - D_SUP; }
            else                          { Ap = A2; lda = D_IND;  kk = k0 - D_SUP - D_ANOM; }
            #pragma unroll
            for (int t = 0; t < BM * 8 / THREADS; t++) {
                int idx = tid + t * THREADS;
                int row = idx >> 3, q = idx & 7;
                float4 v = *(const float4*)(Ap + (size_t)(m0 + row) * lda + kk + q * 4);
                __nv_bfloat16 hx = __float2bfloat16(v.x), hy = __float2bfloat16(v.y);
                __nv_bfloat16 hz = __float2bfloat16(v.z), hw = __float2bfloat16(v.w);
                __nv_bfloat162 h01 = {hx, hy}, h23 = {hz, hw};
                __nv_bfloat162 l01 = __floats2bfloat162_rn(v.x - __bfloat162float(hx),
                                                           v.y - __bfloat162float(hy));
                __nv_bfloat162 l23 = __floats2bfloat162_rn(v.z - __bfloat162float(hz),
                                                           v.w - __bfloat162float(hw));
                int off = row * LDS + q * 4;
                *(__nv_bfloat162*)(sAh + off) = h01;
                *(__nv_bfloat162*)(sAh + off + 2) = h23;
                *(__nv_bfloat162*)(sAl + off) = l01;
                *(__nv_bfloat162*)(sAl + off + 2) = l23;
            }
        }
        #pragma unroll
        for (int t = 0; t < BN * 8 / THREADS; t++) {
            int idx = tid + t * THREADS;
            int half = idx >= BN * 4;
            int cc = half ? idx - BN * 4 : idx;
            int row = cc >> 2, q = cc & 3;
            const __nv_bfloat16* src = (half ? Bl : Bh) + (size_t)(n0 + row) * K + k0 + q * 8;
            *(uint4*)((half ? sBl : sBh) + row * LDS + q * 8) = *(const uint4*)src;
        }
        __syncthreads();

        #pragma unroll
        for (int kq = 0; kq < 2; kq++) {
            uint32_t a_h[2][4], a_l[2][4], bfr[8][2];
            const int colh = kq * 16 + ((lane >> 4) << 3);
            #pragma unroll
            for (int mt = 0; mt < 2; mt++) {
                int row = warpM + mt * 16 + (lane & 15);
                ldsm4(a_h[mt], aAh + (uint32_t)(row * LDS + colh) * 2);
                ldsm4(a_l[mt], aAl + (uint32_t)(row * LDS + colh) * 2);
            }
            #pragma unroll
            for (int nt2 = 0; nt2 < 4; nt2++) {
                int row = warpN + nt2 * 16 + (lane & 15);
                uint32_t r[4];
                ldsm4(r, aBh + (uint32_t)(row * LDS + colh) * 2);
                bfr[2 * nt2][0] = r[0]; bfr[2 * nt2][1] = r[2];
                bfr[2 * nt2 + 1][0] = r[1]; bfr[2 * nt2 + 1][1] = r[3];
            }
            #pragma unroll
            for (int mt = 0; mt < 2; mt++)
                #pragma unroll
                for (int nt = 0; nt < 8; nt++) mma_bf16(acc[mt][nt], a_h[mt], bfr[nt]);
            #pragma unroll
            for (int mt = 0; mt < 2; mt++)
                #pragma unroll
                for (int nt = 0; nt < 8; nt++) mma_bf16(acc[mt][nt], a_l[mt], bfr[nt]);
            #pragma unroll
            for (int nt2 = 0; nt2 < 4; nt2++) {
                int row = warpN + nt2 * 16 + (lane & 15);
                uint32_t r[4];
                ldsm4(r, aBl + (uint32_t)(row * LDS + colh) * 2);
                bfr[2 * nt2][0] = r[0]; bfr[2 * nt2][1] = r[2];
                bfr[2 * nt2 + 1][0] = r[1]; bfr[2 * nt2 + 1][1] = r[3];
            }
            #pragma unroll
            for (int mt = 0; mt < 2; mt++)
                #pragma unroll
                for (int nt = 0; nt < 8; nt++) mma_bf16(acc[mt][nt], a_h[mt], bfr[nt]);
        }
    }

    #pragma unroll
    for (int mt = 0; mt < 2; mt++) {
        const int r0 = m0 + warpM + mt * 16 + (lane >> 2);
        #pragma unroll
        for (int nt = 0; nt < 8; nt++) {
            const int cc = n0 + warpN + nt * 8 + ((lane & 3) << 1);
            float2 bv = *(const float2*)(bias + cc);
            float v00 = fmaxf(acc[mt][nt][0] + bv.x, 0.f);
            float v01 = fmaxf(acc[mt][nt][1] + bv.y, 0.f);
            float v10 = fmaxf(acc[mt][nt][2] + bv.x, 0.f);
            float v11 = fmaxf(acc[mt][nt][3] + bv.y, 0.f);
            __nv_bfloat16 h00 = __float2bfloat16(v00), h01 = __float2bfloat16(v01);
            __nv_bfloat16 h10 = __float2bfloat16(v10), h11 = __float2bfloat16(v11);
            __nv_bfloat162 hi0 = {h00, h01}, hi1 = {h10, h11};
            __nv_bfloat162 lo0 = __floats2bfloat162_rn(v00 - __bfloat162float(h00),
                                                       v01 - __bfloat162float(h01));
            __nv_bfloat162 lo1 = __floats2bfloat162_rn(v10 - __bfloat162float(h10),
                                                       v11 - __bfloat162float(h11));
            *(__nv_bfloat162*)(Oh + (size_t)r0 * Nout + cc) = hi0;
            *(__nv_bfloat162*)(Ol + (size_t)r0 * Nout + cc) = lo0;
            *(__nv_bfloat162*)(Oh + (size_t)(r0 + 8) * Nout + cc) = hi1;
            *(__nv_bfloat162*)(Ol + (size_t)(r0 + 8) * Nout + cc) = lo1;
        }
    }
}

// ===========================================================================
// Fused tail: GEMM2 + 12 consolidator layers + final retrieval, one kernel.
// 512 threads = 16 warps (4x4 warp grid). CTA owns 128 rows.
// Activations resident in smem as bf16 hi/lo. 3-pass hi/lo HMMA everywhere.
// ===========================================================================
#define LDA 136
#define TAIL_SMEM ((128 * LDA * 2 + 256 * LDA * 2) * 2 + 256 * 4)

__global__ __launch_bounds__(512, 1) void fused_tail(
    const __nv_bfloat16* __restrict__ h1h, const __nv_bfloat16* __restrict__ h1l,
    const __nv_bfloat16* __restrict__ Wh2, const __nv_bfloat16* __restrict__ Wl2,
    const float* __restrict__ b2,
    const __nv_bfloat16* __restrict__ WhC, const __nv_bfloat16* __restrict__ WlC,
    const float* __restrict__ consB,
    const __nv_bfloat16* __restrict__ WfH, const __nv_bfloat16* __restrict__ WfL,
    const float* __restrict__ retB, const float* __restrict__ aw,
    float* __restrict__ out) {
    extern __shared__ __nv_bfloat16 sm[];
    __nv_bfloat16* sAh = sm;                  // 128*LDA
    __nv_bfloat16* sAl = sAh + 128 * LDA;
    __nv_bfloat16* sWh = sAl + 128 * LDA;     // 256*LDA (also 128*264 for GEMM2)
    __nv_bfloat16* sWl = sWh + 256 * LDA;
    float* wsum = (float*)(sWl + 256 * LDA);  // 128
    float* saw  = wsum + 128;                 // 128

    const int tid = threadIdx.x;
    const int wid = tid >> 5, lane = tid & 31;
    const int wm = wid & 3;                   // row stripe (32 rows)
    const int wn = wid >> 2;                  // col stripe
    const int m0 = blockIdx.x * 128;

    const uint32_t aAh = smem_u32(sAh), aAl = smem_u32(sAl);
    const uint32_t aWh = smem_u32(sWh), aWl = smem_u32(sWl);

    if (tid < 128) saw[tid] = aw[m0 + tid];

    // ---------------- GEMM2: s = relu(h1 @ W2 + b2), K=256 ----------------
    // load W2 (stride 264)
    #pragma unroll
    for (int t = 0; t < 16; t++) {
        int idx = tid + t * 512;
        int half = idx >= 4096;
        int cc = idx & 4095;
        int row = cc >> 5, q = cc & 31;
        const __nv_bfloat16* src = (half ? Wl2 : Wh2) + (size_t)row * H1 + q * 8;
        *(uint4*)((half ? sWl : sWh) + row * 264 + q * 8) = *(const uint4*)src;
    }

    float acc4[2][4][4];
    #pragma unroll
    for (int i = 0; i < 2; i++)
        #pragma unroll
        for (int j = 0; j < 4; j++)
            #pragma unroll
            for (int q = 0; q < 4; q++) acc4[i][j][q] = 0.f;

    for (int kc = 0; kc < 2; kc++) {
        __syncthreads();
        // load h1 chunk [128 x 128] hi/lo
        #pragma unroll
        for (int t = 0; t < 8; t++) {
            int idx = tid + t * 512;
            int half = idx >= 2048;
            int cc = idx & 2047;
            int row = cc >> 4, q = cc & 15;
            const __nv_bfloat16* src = (half ? h1l : h1h) + (size_t)(m0 + row) * H1 + kc * 128 + q * 8;
            *(uint4*)((half ? sAl : sAh) + row * LDA + q * 8) = *(const uint4*)src;
        }
        __syncthreads();
        #pragma unroll
        for (int ch = 0; ch < 8; ch++) {
            const int colh = ch * 16 + ((lane >> 4) << 3);
            const int colhB = kc * 128 + colh;
            uint32_t a_h[2][4], a_l[2][4], bfr[4][2];
            #pragma unroll
            for (int mt = 0; mt < 2; mt++) {
                int row = wm * 32 + mt * 16 + (lane & 15);
                ldsm4(a_h[mt], aAh + (uint32_t)(row * LDA + colh) * 2);
                ldsm4(a_l[mt], aAl + (uint32_t)(row * LDA + colh) * 2);
            }
            #pragma unroll
            for (int nt2 = 0; nt2 < 2; nt2++) {
                int row = wn * 32 + nt2 * 16 + (lane & 15);
                uint32_t r[4];
                ldsm4(r, aWh + (uint32_t)(row * 264 + colhB) * 2);
                bfr[2 * nt2][0] = r[0]; bfr[2 * nt2][1] = r[2];
                bfr[2 * nt2 + 1][0] = r[1]; bfr[2 * nt2 + 1][1] = r[3];
            }
            #pragma unroll
            for (int mt = 0; mt < 2; mt++)
                #pragma unroll
                for (int nt = 0; nt < 4; nt++) mma_bf16(acc4[mt][nt], a_h[mt], bfr[nt]);
            #pragma unroll
            for (int mt = 0; mt < 2; mt++)
                #pragma unroll
                for (int nt = 0; nt < 4; nt++) mma_bf16(acc4[mt][nt], a_l[mt], bfr[nt]);
            #pragma unroll
            for (int nt2 = 0; nt2 < 2; nt2++) {
                int row = wn * 32 + nt2 * 16 + (lane & 15);
                uint32_t r[4];
                ldsm4(r, aWl + (uint32_t)(row * 264 + colhB) * 2);
                bfr[2 * nt2][0] = r[0]; bfr[2 * nt2][1] = r[2];
                bfr[2 * nt2 + 1][0] = r[1]; bfr[2 * nt2 + 1][1] = r[3];
            }
            #pragma unroll
            for (int mt = 0; mt < 2; mt++)
                #pragma unroll
                for (int nt = 0; nt < 4; nt++) mma_bf16(acc4[mt][nt], a_h[mt], bfr[nt]);
        }
    }
    // epilogue -> write act into sA (bias b2)
    __syncthreads();
    #pragma unroll
    for (int mt = 0; mt < 2; mt++) {
        const int row = wm * 32 + mt * 16 + (lane >> 2);
        #pragma unroll
        for (int nt = 0; nt < 4; nt++) {
            const int col = wn * 32 + nt * 8 + ((lane & 3) << 1);
            float2 bv = *(const float2*)(b2 + col);
            float v00 = fmaxf(acc4[mt][nt][0] + bv.x, 0.f);
            float v01 = fmaxf(acc4[mt][nt][1] + bv.y, 0.f);
            float v10 = fmaxf(acc4[mt][nt][2] + bv.x, 0.f);
            float v11 = fmaxf(acc4[mt][nt][3] + bv.y, 0.f);
            __nv_bfloat16 h00 = __float2bfloat16(v00), h01 = __float2bfloat16(v01);
            __nv_bfloat16 h10 = __float2bfloat16(v10), h11 = __float2bfloat16(v11);
            __nv_bfloat162 hi0 = {h00, h01}, hi1 = {h10, h11};
            __nv_bfloat162 lo0 = __floats2bfloat162_rn(v00 - __bfloat162float(h00),
                                                       v01 - __bfloat162float(h01));
            __nv_bfloat162 lo1 = __floats2bfloat162_rn(v10 - __bfloat162float(h10),
                                                       v11 - __bfloat162float(h11));
            *(__nv_bfloat162*)(sAh + row * LDA + col) = hi0;
            *(__nv_bfloat162*)(sAl + row * LDA + col) = lo0;
            *(__nv_bfloat162*)(sAh + (row + 8) * LDA + col) = hi1;
            *(__nv_bfloat162*)(sAl + (row + 8) * LDA + col) = lo1;
        }
    }

    // ---------------- 12 consolidator layers (smem -> smem) ----------------
    for (int l = 0; l < DEPTH; l++) {
        __syncthreads();
        #pragma unroll
        for (int t = 0; t < 8; t++) {
            int idx = tid + t * 512;
            int half = idx >= 2048;
            int cc = idx & 2047;
            int row = cc >> 4, q = cc & 15;
            const __nv_bfloat16* src = (half ? WlC : WhC) + (size_t)l * FEAT * FEAT
                                     + (size_t)row * FEAT + q * 8;
            *(uint4*)((half ? sWl : sWh) + row * LDA + q * 8) = *(const uint4*)src;
        }
        __syncthreads();
        #pragma unroll
        for (int i = 0; i < 2; i++)
            #pragma unroll
            for (int j = 0; j < 4; j++)
                #pragma unroll
                for (int q = 0; q < 4; q++) acc4[i][j][q] = 0.f;
        #pragma unroll
        for (int ch = 0; ch < 8; ch++) {
            const int colh = ch * 16 + ((lane >> 4) << 3);
            uint32_t a_h[2][4], a_l[2][4], bfr[4][2];
            #pragma unroll
            for (int mt = 0; mt < 2; mt++) {
                int row = wm * 32 + mt * 16 + (lane & 15);
                ldsm4(a_h[mt], aAh + (uint32_t)(row * LDA + colh) * 2);
                ldsm4(a_l[mt], aAl + (uint32_t)(row * LDA + colh) * 2);
            }
            #pragma unroll
            for (int nt2 = 0; nt2 < 2; nt2++) {
                int row = wn * 32 + nt2 * 16 + (lane & 15);
                uint32_t r[4];
                ldsm4(r, aWh + (uint32_t)(row * LDA + colh) * 2);
                bfr[2 * nt2][0] = r[0]; bfr[2 * nt2][1] = r[2];
                bfr[2 * nt2 + 1][0] = r[1]; bfr[2 * nt2 + 1][1] = r[3];
            }
            #pragma unroll
            for (int mt = 0; mt < 2; mt++)
                #pragma unroll
                for (int nt = 0; nt < 4; nt++) mma_bf16(acc4[mt][nt], a_h[mt], bfr[nt]);
            #pragma unroll
            for (int mt = 0; mt < 2; mt++)
                #pragma unroll
                for (int nt = 0; nt < 4; nt++) mma_bf16(acc4[mt][nt], a_l[mt], bfr[nt]);
            #pragma unroll
            for (int nt2 = 0; nt2 < 2; nt2++) {
                int row = wn * 32 + nt2 * 16 + (lane & 15);
                uint32_t r[4];
                ldsm4(r, aWl + (uint32_t)(row * LDA + colh) * 2);
                bfr[2 * nt2][0] = r[0]; bfr[2 * nt2][1] = r[2];
                bfr[2 * nt2 + 1][0] = r[1]; bfr[2 * nt2 + 1][1] = r[3];
            }
            #pragma unroll
            for (int mt = 0; mt < 2; mt++)
                #pragma unroll
                for (int nt = 0; nt < 4; nt++) mma_bf16(acc4[mt][nt], a_h[mt], bfr[nt]);
        }
        __syncthreads();
        #pragma unroll
        for (int mt = 0; mt < 2; mt++) {
            const int row = wm * 32 + mt * 16 + (lane >> 2);
            #pragma unroll
            for (int nt = 0; nt < 4; nt++) {
                const int col = wn * 32 + nt * 8 + ((lane & 3) << 1);
                float2 bv = *(const float2*)(consB + (size_t)l * FEAT + col);
                float v00 = fmaxf(acc4[mt][nt][0] + bv.x, 0.f);
                float v01 = fmaxf(acc4[mt][nt][1] + bv.y, 0.f);
                float v10 = fmaxf(acc4[mt][nt][2] + bv.x, 0.f);
                float v11 = fmaxf(acc4[mt][nt][3] + bv.y, 0.f);
                __nv_bfloat16 h00 = __float2bfloat16(v00), h01 = __float2bfloat16(v01);
                __nv_bfloat16 h10 = __float2bfloat16(v10), h11 = __float2bfloat16(v11);
                __nv_bfloat162 hi0 = {h00, h01}, hi1 = {h10, h11};
                __nv_bfloat162 lo0 = __floats2bfloat162_rn(v00 - __bfloat162float(h00),
                                                           v01 - __bfloat162float(h01));
                __nv_bfloat162 lo1 = __floats2bfloat162_rn(v10 - __bfloat162float(h10),
                                                           v11 - __bfloat162float(h11));
                *(__nv_bfloat162*)(sAh + row * LDA + col) = hi0;
                *(__nv_bfloat162*)(sAl + row * LDA + col) = lo0;
                *(__nv_bfloat162*)(sAh + (row + 8) * LDA + col) = hi1;
                *(__nv_bfloat162*)(sAl + (row + 8) * LDA + col) = lo1;
            }
        }
    }

    // ---------------- final: per k, G = state @ [retW_k^T ; Mk^T]^T --------
    const float cfac = 0.42f * 1.8f / (float)CAP;
    for (int k = 0; k < NCOND; k++) {
        __syncthreads();
        if (tid < 128) wsum[tid] = 0.f;
        #pragma unroll
        for (int t = 0; t < 16; t++) {
            int idx = tid + t * 512;
            int half = idx >= 4096;
            int cc = idx & 4095;
            int row = cc >> 4, q = cc & 15;   // row 0..255
            const __nv_bfloat16* src = (half ? WfL : WfH) + (size_t)k * 256 * FEAT
                                     + (size_t)row * FEAT + q * 8;
            *(uint4*)((half ? sWl : sWh) + row * LDA + q * 8) = *(const uint4*)src;
        }
        __syncthreads();

        float acc8[2][8][4];
        #pragma unroll
        for (int i = 0; i < 2; i++)
            #pragma unroll
            for (int j = 0; j < 8; j++)
                #pragma unroll
                for (int q = 0; q < 4; q++) acc8[i][j][q] = 0.f;

        #pragma unroll
        for (int ch = 0; ch < 8; ch++) {
            const int colh = ch * 16 + ((lane >> 4) << 3);
            uint32_t a_h[2][4], a_l[2][4], bfr[8][2];
            #pragma unroll
            for (int mt = 0; mt < 2; mt++) {
                int row = wm * 32 + mt * 16 + (lane & 15);
                ldsm4(a_h[mt], aAh + (uint32_t)(row * LDA + colh) * 2);
                ldsm4(a_l[mt], aAl + (uint32_t)(row * LDA + colh) * 2);
            }
            #pragma unroll
            for (int nt2 = 0; nt2 < 4; nt2++) {
                int row = wn * 64 + nt2 * 16 + (lane & 15);
                uint32_t r[4];
                ldsm4(r, aWh + (uint32_t)(row * LDA + colh) * 2);
                bfr[2 * nt2][0] = r[0]; bfr[2 * nt2][1] = r[2];
                bfr[2 * nt2 + 1][0] = r[1]; bfr[2 * nt2 + 1][1] = r[3];
            }
            #pragma unroll
            for (int mt = 0; mt < 2; mt++)
                #pragma unroll
                for (int nt = 0; nt < 8; nt++) mma_bf16(acc8[mt][nt], a_h[mt], bfr[nt]);
            #pragma unroll
            for (int mt = 0; mt < 2; mt++)
                #pragma unroll
                for (int nt = 0; nt < 8; nt++) mma_bf16(acc8[mt][nt], a_l[mt], bfr[nt]);
            #pragma unroll
            for (int nt2 = 0; nt2 < 4; nt2++) {
                int row = wn * 64 + nt2 * 16 + (lane & 15);
                uint32_t r[4];
                ldsm4(r, aWl + (uint32_t)(row * LDA + colh) * 2);
                bfr[2 * nt2][0] = r[0]; bfr[2 * nt2][1] = r[2];
                bfr[2 * nt2 + 1][0] = r[1]; bfr[2 * nt2 + 1][1] = r[3];
            }
            #pragma unroll
            for (int mt = 0; mt < 2; mt++)
                #pragma unroll
                for (int nt = 0; nt < 8; nt++) mma_bf16(acc8[mt][nt], a_h[mt], bfr[nt]);
        }

        // quadratic form: warps wn>=2 hold t-cols (128..255)
        if (wn >= 2) {
            #pragma unroll
            for (int mt = 0; mt < 2; mt++) {
                const int r1 = wm * 32 + mt * 16 + (lane >> 2);
                float p1 = 0.f, p2 = 0.f;
                #pragma unroll
                for (int nt = 0; nt < 8; nt++) {
                    const int e0 = (wn - 2) * 64 + nt * 8 + ((lane & 3) << 1);
                    float m00 = __bfloat162float(sAh[r1 * LDA + e0]) +
                                __bfloat162float(sAl[r1 * LDA + e0]);
                    float m01 = __bfloat162float(sAh[r1 * LDA + e0 + 1]) +
                                __bfloat162float(sAl[r1 * LDA + e0 + 1]);
                    float m10 = __bfloat162float(sAh[(r1 + 8) * LDA + e0]) +
                                __bfloat162float(sAl[(r1 + 8) * LDA + e0]);
                    float m11 = __bfloat162float(sAh[(r1 + 8) * LDA + e0 + 1]) +
                                __bfloat162float(sAl[(r1 + 8) * LDA + e0 + 1]);
                    p1 += acc8[mt][nt][0] * m00 + acc8[mt][nt][1] * m01;
                    p2 += acc8[mt][nt][2] * m10 + acc8[mt][nt][3] * m11;
                }
                atomicAdd(&wsum[r1], p1);
                atomicAdd(&wsum[r1 + 8], p2);
            }
        }
        __syncthreads();
        if (tid < 128) wsum[tid] = wsum[tid] * cfac + 0.3f * saw[tid];
        __syncthreads();

        // writers: warps wn<2 hold retrieved cols (0..127)
        if (wn < 2) {
            #pragma unroll
            for (int mt = 0; mt < 2; mt++) {
                const int rl = wm * 32 + mt * 16 + (lane >> 2);
                const float w1 = wsum[rl], w2 = wsum[rl + 8];
                #pragma unroll
                for (int nt = 0; nt < 8; nt++) {
                    const int col = wn * 64 + nt * 8 + ((lane & 3) << 1);
                    float2 bv = *(const float2*)(retB + (size_t)k * FEAT + col);
                    size_t base1 = (size_t)(m0 + rl) * (NCOND * FEAT) + (size_t)k * FEAT + col;
                    size_t base2 = (size_t)(m0 + rl + 8) * (NCOND * FEAT) + (size_t)k * FEAT + col;
                    float2 o1 = make_float2((acc8[mt][nt][0] + bv.x) * w1,
                                            (acc8[mt][nt][1] + bv.y) * w1);
                    float2 o2 = make_float2((acc8[mt][nt][2] + bv.x) * w2,
                                            (acc8[mt][nt][3] + bv.y) * w2);
                    *(float2*)(out + base1) = o1;
                    *(float2*)(out + base2) = o2;
                }
            }
        }
    }
}

// ===========================================================================
extern "C" void kernel_launch(void* const* d_in, const int* in_sizes, int n_in,
                              void* d_out, int out_size) {
    const float* sup  = (const float*)d_in[0];
    const float* anom = (const float*)d_in[1];
    const float* ind  = (const float*)d_in[2];
    const float* ipW1 = (const float*)d_in[3];
    const float* ipb1 = (const float*)d_in[4];
    const float* ipW2 = (const float*)d_in[5];
    const float* ipb2 = (const float*)d_in[6];
    const float* consW = (const float*)d_in[7];
    const float* consB = (const float*)d_in[8];
    const float* refp = (const float*)d_in[9];
    const float* objp = (const float*)d_in[10];
    const float* retW = (const float*)d_in[11];
    const float* retB = (const float*)d_in[12];
    float* out = (float*)d_out;

    __nv_bfloat16 *Wh1, *Wl1, *Wh2, *Wl2, *WhC, *WlC, *h1h, *h1l, *WfH, *WfL;
    float *aw;
    cudaGetSymbolAddress((void**)&Wh1, g_Wh1);
    cudaGetSymbolAddress((void**)&Wl1, g_Wl1);
    cudaGetSymbolAddress((void**)&Wh2, g_Wh2);
    cudaGetSymbolAddress((void**)&Wl2, g_Wl2);
    cudaGetSymbolAddress((void**)&WhC, g_WhC);
    cudaGetSymbolAddress((void**)&WlC, g_WlC);
    cudaGetSymbolAddress((void**)&h1h, g_h1h);
    cudaGetSymbolAddress((void**)&h1l, g_h1l);
    cudaGetSymbolAddress((void**)&WfH, g_WfinH);
    cudaGetSymbolAddress((void**)&WfL, g_WfinL);
    cudaGetSymbolAddress((void**)&aw, g_aw);

    const int SM_G1 = (128 + 256) * 40 * 2 * 2;  // 61440
    cudaFuncSetAttribute(mma_gemm1<128, 256, 512>,
                         cudaFuncAttributeMaxDynamicSharedMemorySize, SM_G1);
    cudaFuncSetAttribute(fused_tail,
                         cudaFuncAttributeMaxDynamicSharedMemorySize, TAIL_SMEM);

    // preps (independent)
    aw_kernel<<<BB * 32 / 256, 256>>>(anom, aw);
    mkfin_kernel<<<NCOND, 256>>>(refp, objp, WfH, WfL);
    tsplit_kernel<<<dim3(D_IN / 32, H1 / 32, 1), dim3(32, 8)>>>(ipW1, Wh1, Wl1, D_IN, H1, H1 * D_IN);
    tsplit_kernel<<<dim3(H1 / 32, FEAT / 32, 1), dim3(32, 8)>>>(ipW2, Wh2, Wl2, H1, FEAT, FEAT * H1);
    tsplit_kernel<<<dim3(FEAT / 32, FEAT / 32, DEPTH), dim3(32, 8)>>>(consW, WhC, WlC, FEAT, FEAT, FEAT * FEAT);
    // retW^T -> Wfin rows 0..127 (batch stride = 256*128)
    tsplit_kernel<<<dim3(FEAT / 32, FEAT / 32, NCOND), dim3(32, 8)>>>(retW, WfH, WfL, FEAT, FEAT, 256 * FEAT);

    // GEMM1: h1 = relu(concat @ W1 + b1) -> bf16 hi/lo
    mma_gemm1<128, 256, 512><<<dim3(1, BB / 128), 512, SM_G1>>>(
        sup, anom, ind, Wh1, Wl1, ipb1, h1h, h1l, D_IN);

    // fused tail: GEMM2 + 12 layers + final retrieval
    fused_tail<<<BB / 128, 512, TAIL_SMEM>>>(
        h1h, h1l, Wh2, Wl2, ipb2, WhC, WlC, consB, WfH, WfL, retB, aw, out);
}

// round 6
// speedup vs baseline: 3.2549x; 1.0784x over previous
#include <cuda_runtime.h>
#include <cuda_bf16.h>
#include <stdint.h>

#define BB 16384
#define D_SUP 1024
#define D_ANOM 128
#define D_IND 2048
#define D_IN 3200
#define H1 256
#define FEAT 128
#define DEPTH 12
#define NCOND 14
#define CAP 256

// ---------------- scratch (device globals; no allocation allowed) ----------
__device__ __nv_bfloat16 g_Wh1[H1 * D_IN];           // W1^T hi [256][3200]
__device__ __nv_bfloat16 g_Wl1[H1 * D_IN];
__device__ __nv_bfloat16 g_Wh2[FEAT * H1];           // W2^T hi [128][256]
__device__ __nv_bfloat16 g_Wl2[FEAT * H1];
__device__ __nv_bfloat16 g_WhC[DEPTH * FEAT * FEAT]; // consW^T hi [12][128][128]
__device__ __nv_bfloat16 g_WlC[DEPTH * FEAT * FEAT];
__device__ __nv_bfloat16 g_h1h[BB * H1];             // h1 hi/lo [16384][256]
__device__ __nv_bfloat16 g_h1l[BB * H1];
__device__ __nv_bfloat16 g_WfinH[NCOND * 256 * FEAT]; // [k][256][128]: rows 0-127 retW^T, 128-255 Mk^T
__device__ __nv_bfloat16 g_WfinL[NCOND * 256 * FEAT];
__device__ float g_aw[BB];

// ---------------- helpers --------------------------------------------------
__device__ __forceinline__ uint32_t smem_u32(const void* p) {
    uint32_t a;
    asm("{ .reg .u64 t; cvta.to.shared.u64 t, %1; cvt.u32.u64 %0, t; }" : "=r"(a) : "l"(p));
    return a;
}
__device__ __forceinline__ void ldsm4(uint32_t* r, uint32_t addr) {
    asm volatile("ldmatrix.sync.aligned.m8n8.x4.shared.b16 {%0,%1,%2,%3}, [%4];"
                 : "=r"(r[0]), "=r"(r[1]), "=r"(r[2]), "=r"(r[3]) : "r"(addr));
}
__device__ __forceinline__ void mma_bf16(float* c, const uint32_t* a, const uint32_t* b) {
    asm volatile("mma.sync.aligned.m16n8k16.row.col.f32.bf16.bf16.f32 "
                 "{%0,%1,%2,%3}, {%4,%5,%6,%7}, {%8,%9}, {%0,%1,%2,%3};"
                 : "+f"(c[0]), "+f"(c[1]), "+f"(c[2]), "+f"(c[3])
                 : "r"(a[0]), "r"(a[1]), "r"(a[2]), "r"(a[3]), "r"(b[0]), "r"(b[1]));
}
__device__ __forceinline__ void cp16(uint32_t smem, const void* g) {
    asm volatile("cp.async.cg.shared.global [%0], [%1], 16;" :: "r"(smem), "l"(g));
}
#define CP_COMMIT() asm volatile("cp.async.commit_group;" ::: "memory")
#define CP_WAIT0()  asm volatile("cp.async.wait_group 0;" ::: "memory")
#define CP_WAIT1()  asm volatile("cp.async.wait_group 1;" ::: "memory")

// ---------------- aw[b] = mean(|anomaly[b,:]|) -----------------------------
__global__ __launch_bounds__(256) void aw_kernel(const float* __restrict__ anom,
                                                 float* __restrict__ aw) {
    int warp = (blockIdx.x * blockDim.x + threadIdx.x) >> 5;
    int lane = threadIdx.x & 31;
    if (warp >= BB) return;
    float4 v = *(const float4*)(anom + (size_t)warp * D_ANOM + lane * 4);
    float s = fabsf(v.x) + fabsf(v.y) + fabsf(v.z) + fabsf(v.w);
    #pragma unroll
    for (int o = 16; o; o >>= 1) s += __shfl_xor_sync(0xFFFFFFFFu, s, o);
    if (lane == 0) aw[warp] = s * (1.0f / D_ANOM);
}

// ---------------- Mk^T hi/lo into Wfin rows 128-255 ------------------------
__global__ __launch_bounds__(256) void mkfin_kernel(const float* __restrict__ refp,
                                                    const float* __restrict__ objp,
                                                    __nv_bfloat16* __restrict__ WfH,
                                                    __nv_bfloat16* __restrict__ WfL) {
    const int k = blockIdx.x;
    __shared__ float Rs[32][FEAT];
    __shared__ float Os[32][FEAT];
    const int tid = threadIdx.x;
    const int tc = tid & 15;
    const int tr = tid >> 4;
    float acc[8][8] = {};
    const float* rb = refp + (size_t)k * CAP * FEAT;
    const float* ob = objp + (size_t)k * CAP * FEAT;
    for (int c0 = 0; c0 < CAP; c0 += 32) {
        #pragma unroll
        for (int i = tid; i < 32 * FEAT / 4; i += 256) {
            int c = i >> 5, d4 = (i & 31) * 4;
            *(float4*)&Rs[c][d4] = *(const float4*)(rb + (size_t)(c0 + c) * FEAT + d4);
            *(float4*)&Os[c][d4] = *(const float4*)(ob + (size_t)(c0 + c) * FEAT + d4);
        }
        __syncthreads();
        #pragma unroll 8
        for (int c = 0; c < 32; c++) {
            float a[8], b[8];
            #pragma unroll
            for (int i = 0; i < 8; i += 4) *(float4*)&a[i] = *(const float4*)&Rs[c][tr * 8 + i];
            #pragma unroll
            for (int j = 0; j < 8; j += 4) *(float4*)&b[j] = *(const float4*)&Os[c][tc * 8 + j];
            #pragma unroll
            for (int i = 0; i < 8; i++)
                #pragma unroll
                for (int j = 0; j < 8; j++) acc[i][j] += a[i] * b[j];
        }
        __syncthreads();
    }
    #pragma unroll
    for (int j = 0; j < 8; j++) {
        int e = tc * 8 + j;
        __nv_bfloat16 hv[8], lv[8];
        #pragma unroll
        for (int i = 0; i < 8; i++) {
            float v = acc[i][j];
            __nv_bfloat16 hi = __float2bfloat16(v);
            hv[i] = hi;
            lv[i] = __float2bfloat16(v - __bfloat162float(hi));
        }
        size_t base = (size_t)k * 256 * FEAT + (size_t)(128 + e) * FEAT + tr * 8;
        *(uint4*)(WfH + base) = *(uint4*)hv;
        *(uint4*)(WfL + base) = *(uint4*)lv;
    }
}

// ---------------- transpose + hi/lo split:  dst[n][k] = W[k][n] ------------
__global__ __launch_bounds__(256) void tsplit_kernel(const float* __restrict__ W,
                                                     __nv_bfloat16* __restrict__ Wh,
                                                     __nv_bfloat16* __restrict__ Wl,
                                                     int K, int N, int dstBatchStride) {
    const int batch = blockIdx.z;
    W += (size_t)batch * K * N;
    Wh += (size_t)batch * dstBatchStride;
    Wl += (size_t)batch * dstBatchStride;
    __shared__ float t[32][33];
    const int k0 = blockIdx.x * 32;
    const int n0 = blockIdx.y * 32;
    const int tx = threadIdx.x, ty = threadIdx.y;
    #pragma unroll
    for (int i = 0; i < 4; i++)
        t[ty + 8 * i][tx] = W[(size_t)(k0 + ty + 8 * i) * N + n0 + tx];
    __syncthreads();
    #pragma unroll
    for (int i = 0; i < 4; i++) {
        int n = n0 + ty + 8 * i;
        int k = k0 + tx;
        float v = t[tx][ty + 8 * i];
        __nv_bfloat16 hi = __float2bfloat16(v);
        __nv_bfloat16 lo = __float2bfloat16(v - __bfloat162float(hi));
        Wh[(size_t)n * K + k] = hi;
        Wl[(size_t)n * K + k] = lo;
    }
}

// ===========================================================================
// GEMM1 v2: cp.async 2-stage pipelined HMMA.
//   h1 = relu(concat(sup,anom,ind) @ W1 + b1) -> bf16 hi/lo
// ===========================================================================
#define G1_BUF 79872
#define G1_OF  0
#define G1_OAH 18432
#define G1_OAL 28672
#define G1_OWH 38912
#define G1_OWL 59392
#define G1_SMEM (2 * G1_BUF)
#define G1_NIT (D_IN / 32)

__global__ __launch_bounds__(512, 1) void gemm1_v2(
    const float* __restrict__ A0, const float* __restrict__ A1,
    const float* __restrict__ A2,
    const __nv_bfloat16* __restrict__ Bh, const __nv_bfloat16* __restrict__ Bl,
    const float* __restrict__ bias,
    __nv_bfloat16* __restrict__ Oh, __nv_bfloat16* __restrict__ Ol) {
    extern __shared__ char sm[];
    const uint32_t sb = smem_u32(sm);
    const int tid = threadIdx.x;
    const int wid = tid >> 5, lane = tid & 31;
    const int warpM = (wid & 3) * 32;
    const int warpN = (wid >> 2) * 64;
    const int m0 = blockIdx.x * 128;

    float acc[2][8][4];
    #pragma unroll
    for (int i = 0; i < 2; i++)
        #pragma unroll
        for (int j = 0; j < 8; j++)
            #pragma unroll
            for (int q = 0; q < 4; q++) acc[i][j][q] = 0.f;

    auto issue = [&](int it, int b) {
        const int k0 = it * 32;
        const float* Ap; int lda, kk;
        if (k0 < D_SUP)               { Ap = A0; lda = D_SUP;  kk = k0; }
        else if (k0 < D_SUP + D_ANOM) { Ap = A1; lda = D_ANOM; kk = k0 - D_SUP; }
        else                          { Ap = A2; lda = D_IND;  kk = k0 - D_SUP - D_ANOM; }
        const uint32_t bb = sb + b * G1_BUF;
        #pragma unroll
        for (int t = 0; t < 2; t++) {
            int idx = tid + t * 512;          // 1024 chunks of A (fp32)
            int row = idx >> 3, q = idx & 7;
            cp16(bb + G1_OF + row * 144 + q * 16,
                 Ap + (size_t)(m0 + row) * lda + kk + q * 4);
        }
        #pragma unroll
        for (int t = 0; t < 4; t++) {
            int idx = tid + t * 512;          // 2048 chunks of W (hi then lo)
            int half = idx >= 1024;
            int cc = idx & 1023;
            int row = cc >> 2, q = cc & 3;
            cp16(bb + (half ? G1_OWL : G1_OWH) + row * 80 + q * 16,
                 (half ? Bl : Bh) + (size_t)row * D_IN + it * 32 + q * 8);
        }
        CP_COMMIT();
    };

    issue(0, 0);

    for (int it = 0; it < G1_NIT; it++) {
        const int b = it & 1;
        const uint32_t bb = sb + b * G1_BUF;
        CP_WAIT0();
        __syncthreads();                       // buf b ready; buf b^1 fully consumed
        if (it + 1 < G1_NIT) issue(it + 1, b ^ 1);

        // convert fp32 stage -> bf16 hi/lo
        #pragma unroll
        for (int t = 0; t < 2; t++) {
            int idx = tid + t * 512;
            int row = idx >> 3, q = idx & 7;
            float4 v = *(const float4*)(sm + (size_t)b * G1_BUF + G1_OF + row * 144 + q * 16);
            __nv_bfloat16 hx = __float2bfloat16(v.x), hy = __float2bfloat16(v.y);
            __nv_bfloat16 hz = __float2bfloat16(v.z), hw = __float2bfloat16(v.w);
            __nv_bfloat162 h01 = {hx, hy}, h23 = {hz, hw};
            __nv_bfloat162 l01 = __floats2bfloat162_rn(v.x - __bfloat162float(hx),
                                                       v.y - __bfloat162float(hy));
            __nv_bfloat162 l23 = __floats2bfloat162_rn(v.z - __bfloat162float(hz),
                                                       v.w - __bfloat162float(hw));
            size_t off = (size_t)b * G1_BUF + (row * 40 + q * 4) * 2;
            *(__nv_bfloat162*)(sm + off + G1_OAH) = h01;
            *(__nv_bfloat162*)(sm + off + G1_OAH + 4) = h23;
            *(__nv_bfloat162*)(sm + off + G1_OAL) = l01;
            *(__nv_bfloat162*)(sm + off + G1_OAL + 4) = l23;
        }
        __syncthreads();

        const uint32_t aAh = bb + G1_OAH, aAl = bb + G1_OAL;
        const uint32_t aBh = bb + G1_OWH, aBl = bb + G1_OWL;
        #pragma unroll
        for (int kq = 0; kq < 2; kq++) {
            uint32_t a_h[2][4], a_l[2][4], bfr[8][2];
            const int colh = kq * 16 + ((lane >> 4) << 3);
            #pragma unroll
            for (int mt = 0; mt < 2; mt++) {
                int row = warpM + mt * 16 + (lane & 15);
                ldsm4(a_h[mt], aAh + (uint32_t)(row * 40 + colh) * 2);
                ldsm4(a_l[mt], aAl + (uint32_t)(row * 40 + colh) * 2);
            }
            #pragma unroll
            for (int nt2 = 0; nt2 < 4; nt2++) {
                int row = warpN + nt2 * 16 + (lane & 15);
                uint32_t r[4];
                ldsm4(r, aBh + (uint32_t)(row * 40 + colh) * 2);
                bfr[2 * nt2][0] = r[0]; bfr[2 * nt2][1] = r[2];
                bfr[2 * nt2 + 1][0] = r[1]; bfr[2 * nt2 + 1][1] = r[3];
            }
            #pragma unroll
            for (int mt = 0; mt < 2; mt++)
                #pragma unroll
                for (int nt = 0; nt < 8; nt++) mma_bf16(acc[mt][nt], a_h[mt], bfr[nt]);
            #pragma unroll
            for (int mt = 0; mt < 2; mt++)
                #pragma unroll
                for (int nt = 0; nt < 8; nt++) mma_bf16(acc[mt][nt], a_l[mt], bfr[nt]);
            #pragma unroll
            for (int nt2 = 0; nt2 < 4; nt2++) {
                int row = warpN + nt2 * 16 + (lane & 15);
                uint32_t r[4];
                ldsm4(r, aBl + (uint32_t)(row * 40 + colh) * 2);
                bfr[2 * nt2][0] = r[0]; bfr[2 * nt2][1] = r[2];
                bfr[2 * nt2 + 1][0] = r[1]; bfr[2 * nt2 + 1][1] = r[3];
            }
            #pragma unroll
            for (int mt = 0; mt < 2; mt++)
                #pragma unroll
                for (int nt = 0; nt < 8; nt++) mma_bf16(acc[mt][nt], a_h[mt], bfr[nt]);
        }
    }

    #pragma unroll
    for (int mt = 0; mt < 2; mt++) {
        const int r0 = m0 + warpM + mt * 16 + (lane >> 2);
        #pragma unroll
        for (int nt = 0; nt < 8; nt++) {
            const int cc = warpN + nt * 8 + ((lane & 3) << 1);
            float2 bv = *(const float2*)(bias + cc);
            float v00 = fmaxf(acc[mt][nt][0] + bv.x, 0.f);
            float v01 = fmaxf(acc[mt][nt][1] + bv.y, 0.f);
            float v10 = fmaxf(acc[mt][nt][2] + bv.x, 0.f);
            float v11 = fmaxf(acc[mt][nt][3] + bv.y, 0.f);
            __nv_bfloat16 h00 = __float2bfloat16(v00), h01 = __float2bfloat16(v01);
            __nv_bfloat16 h10 = __float2bfloat16(v10), h11 = __float2bfloat16(v11);
            __nv_bfloat162 hi0 = {h00, h01}, hi1 = {h10, h11};
            __nv_bfloat162 lo0 = __floats2bfloat162_rn(v00 - __bfloat162float(h00),
                                                       v01 - __bfloat162float(h01));
            __nv_bfloat162 lo1 = __floats2bfloat162_rn(v10 - __bfloat162float(h10),
                                                       v11 - __bfloat162float(h11));
            *(__nv_bfloat162*)(Oh + (size_t)r0 * H1 + cc) = hi0;
            *(__nv_bfloat162*)(Ol + (size_t)r0 * H1 + cc) = lo0;
            *(__nv_bfloat162*)(Oh + (size_t)(r0 + 8) * H1 + cc) = hi1;
            *(__nv_bfloat162*)(Ol + (size_t)(r0 + 8) * H1 + cc) = lo1;
        }
    }
}

// ===========================================================================
// Fused tail v2: GEMM2 + 12 layers + final retrieval, cp.async pipelined.
// ===========================================================================
#define LDA 136
#define TAIL_SMEM ((128 * LDA * 2 + 256 * LDA * 2) * 2 + 256 * 4)

__global__ __launch_bounds__(512, 1) void fused_tail(
    const __nv_bfloat16* __restrict__ h1h, const __nv_bfloat16* __restrict__ h1l,
    const __nv_bfloat16* __restrict__ Wh2, const __nv_bfloat16* __restrict__ Wl2,
    const float* __restrict__ b2,
    const __nv_bfloat16* __restrict__ WhC, const __nv_bfloat16* __restrict__ WlC,
    const float* __restrict__ consB,
    const __nv_bfloat16* __restrict__ WfH, const __nv_bfloat16* __restrict__ WfL,
    const float* __restrict__ retB, const float* __restrict__ aw,
    float* __restrict__ out) {
    extern __shared__ __nv_bfloat16 smt[];
    __nv_bfloat16* sAh = smt;                 // 128*LDA
    __nv_bfloat16* sAl = sAh + 128 * LDA;
    __nv_bfloat16* sWh = sAl + 128 * LDA;     // 256*LDA (2 slots of 128)
    __nv_bfloat16* sWl = sWh + 256 * LDA;
    float* wsum = (float*)(sWl + 256 * LDA);  // 128
    float* saw  = wsum + 128;                 // 128

    const int tid = threadIdx.x;
    const int wid = tid >> 5, lane = tid & 31;
    const int wm = wid & 3;
    const int wn = wid >> 2;
    const int m0 = blockIdx.x * 128;

    const uint32_t aAh = smem_u32(sAh), aAl = smem_u32(sAl);
    const uint32_t aWh = smem_u32(sWh), aWl = smem_u32(sWl);

    auto issueW = [&](const __nv_bfloat16* srcH, const __nv_bfloat16* srcL,
                      int srcStride, int slot) {
        #pragma unroll
        for (int t = 0; t < 8; t++) {
            int idx = tid + t * 512;
            int half = idx >= 2048;
            int cc = idx & 2047;
            int row = cc >> 4, q = cc & 15;
            const __nv_bfloat16* src = (half ? srcL : srcH) + (size_t)row * srcStride + q * 8;
            cp16((half ? aWl : aWh) + (uint32_t)((slot * 128 + row) * LDA + q * 8) * 2, src);
        }
        CP_COMMIT();
    };
    auto issueAct = [&](int kc) {
        #pragma unroll
        for (int t = 0; t < 8; t++) {
            int idx = tid + t * 512;
            int half = idx >= 2048;
            int cc = idx & 2047;
            int row = cc >> 4, q = cc & 15;
            const __nv_bfloat16* src = (half ? h1l : h1h)
                + (size_t)(m0 + row) * H1 + kc * 128 + q * 8;
            cp16((half ? aAl : aAh) + (uint32_t)(row * LDA + q * 8) * 2, src);
        }
        CP_COMMIT();
    };
    auto issueFin = [&](int k) {
        #pragma unroll
        for (int t = 0; t < 16; t++) {
            int idx = tid + t * 512;
            int half = idx >= 4096;
            int cc = idx & 4095;
            int row = cc >> 4, q = cc & 15;
            const __nv_bfloat16* src = (half ? WfL : WfH)
                + (size_t)k * 256 * FEAT + (size_t)row * FEAT + q * 8;
            cp16((half ? aWl : aWh) + (uint32_t)(row * LDA + q * 8) * 2, src);
        }
        CP_COMMIT();
    };

    auto mma128 = [&](float acc4[2][4][4], int slot) {
        const uint32_t base = (uint32_t)(slot * 128 * LDA) * 2;
        #pragma unroll
        for (int ch = 0; ch < 8; ch++) {
            const int colh = ch * 16 + ((lane >> 4) << 3);
            uint32_t a_h[2][4], a_l[2][4], bfr[4][2];
            #pragma unroll
            for (int mt = 0; mt < 2; mt++) {
                int row = wm * 32 + mt * 16 + (lane & 15);
                ldsm4(a_h[mt], aAh + (uint32_t)(row * LDA + colh) * 2);
                ldsm4(a_l[mt], aAl + (uint32_t)(row * LDA + colh) * 2);
            }
            #pragma unroll
            for (int nt2 = 0; nt2 < 2; nt2++) {
                int row = wn * 32 + nt2 * 16 + (lane & 15);
                uint32_t r[4];
                ldsm4(r, aWh + base + (uint32_t)(row * LDA + colh) * 2);
                bfr[2 * nt2][0] = r[0]; bfr[2 * nt2][1] = r[2];
                bfr[2 * nt2 + 1][0] = r[1]; bfr[2 * nt2 + 1][1] = r[3];
            }
            #pragma unroll
            for (int mt = 0; mt < 2; mt++)
                #pragma unroll
                for (int nt = 0; nt < 4; nt++) mma_bf16(acc4[mt][nt], a_h[mt], bfr[nt]);
            #pragma unroll
            for (int mt = 0; mt < 2; mt++)
                #pragma unroll
                for (int nt = 0; nt < 4; nt++) mma_bf16(acc4[mt][nt], a_l[mt], bfr[nt]);
            #pragma unroll
            for (int nt2 = 0; nt2 < 2; nt2++) {
                int row = wn * 32 + nt2 * 16 + (lane & 15);
                uint32_t r[4];
                ldsm4(r, aWl + base + (uint32_t)(row * LDA + colh) * 2);
                bfr[2 * nt2][0] = r[0]; bfr[2 * nt2][1] = r[2];
                bfr[2 * nt2 + 1][0] = r[1]; bfr[2 * nt2 + 1][1] = r[3];
            }
            #pragma unroll
            for (int mt = 0; mt < 2; mt++)
                #pragma unroll
                for (int nt = 0; nt < 4; nt++) mma_bf16(acc4[mt][nt], a_h[mt], bfr[nt]);
        }
    };
    auto epilogue = [&](float acc4[2][4][4], const float* biasp) {
        #pragma unroll
        for (int mt = 0; mt < 2; mt++) {
            const int row = wm * 32 + mt * 16 + (lane >> 2);
            #pragma unroll
            for (int nt = 0; nt < 4; nt++) {
                const int col = wn * 32 + nt * 8 + ((lane & 3) << 1);
                float2 bv = *(const float2*)(biasp + col);
                float v00 = fmaxf(acc4[mt][nt][0] + bv.x, 0.f);
                float v01 = fmaxf(acc4[mt][nt][1] + bv.y, 0.f);
                float v10 = fmaxf(acc4[mt][nt][2] + bv.x, 0.f);
                float v11 = fmaxf(acc4[mt][nt][3] + bv.y, 0.f);
                __nv_bfloat16 h00 = __float2bfloat16(v00), h01 = __float2bfloat16(v01);
                __nv_bfloat16 h10 = __float2bfloat16(v10), h11 = __float2bfloat16(v11);
                __nv_bfloat162 hi0 = {h00, h01}, hi1 = {h10, h11};
                __nv_bfloat162 lo0 = __floats2bfloat162_rn(v00 - __bfloat162float(h00),
                                                           v01 - __bfloat162float(h01));
                __nv_bfloat162 lo1 = __floats2bfloat162_rn(v10 - __bfloat162float(h10),
                                                           v11 - __bfloat162float(h11));
                *(__nv_bfloat162*)(sAh + row * LDA + col) = hi0;
                *(__nv_bfloat162*)(sAl + row * LDA + col) = lo0;
                *(__nv_bfloat162*)(sAh + (row + 8) * LDA + col) = hi1;
                *(__nv_bfloat162*)(sAl + (row + 8) * LDA + col) = lo1;
            }
        }
    };

    if (tid < 128) saw[tid] = aw[m0 + tid];

    // ---------------- GEMM2 (K=256, two 128-chunks) ----------------
    issueW(Wh2, Wl2, H1, 0);         // G1
    issueAct(0);                     // G2
    {
        #pragma unroll
        for (int t = 0; t < 8; t++) {
            int idx = tid + t * 512;
            int half = idx >= 2048;
            int cc = idx & 2047;
            int row = cc >> 4, q = cc & 15;
            const __nv_bfloat16* src = (half ? Wl2 : Wh2) + (size_t)row * H1 + 128 + q * 8;
            cp16((half ? aWl : aWh) + (uint32_t)((128 + row) * LDA + q * 8) * 2, src);
        }
        CP_COMMIT();                 // G3
    }

    float acc4[2][4][4];
    #pragma unroll
    for (int i = 0; i < 2; i++)
        #pragma unroll
        for (int j = 0; j < 4; j++)
            #pragma unroll
            for (int q = 0; q < 4; q++) acc4[i][j][q] = 0.f;

    CP_WAIT1();                      // G1,G2 done
    __syncthreads();
    mma128(acc4, 0);                 // kc=0
    __syncthreads();
    issueAct(1);                     // G4
    issueW(WhC, WlC, FEAT, 0);       // G5: layer 0 weights
    CP_WAIT1();                      // G3,G4 done
    __syncthreads();
    mma128(acc4, 1);                 // kc=1
    __syncthreads();
    epilogue(acc4, b2);
    __syncthreads();

    // ---------------- 12 consolidator layers ----------------
    for (int l = 0; l < DEPTH; l++) {
        if (l + 1 < DEPTH)
            issueW(WhC + (size_t)(l + 1) * FEAT * FEAT,
                   WlC + (size_t)(l + 1) * FEAT * FEAT, FEAT, (l + 1) & 1);
        if (l + 1 < DEPTH) { CP_WAIT1(); } else { CP_WAIT0(); }
        __syncthreads();
        #pragma unroll
        for (int i = 0; i < 2; i++)
            #pragma unroll
            for (int j = 0; j < 4; j++)
                #pragma unroll
                for (int q = 0; q < 4; q++) acc4[i][j][q] = 0.f;
        mma128(acc4, l & 1);
        __syncthreads();
        epilogue(acc4, consB + (size_t)l * FEAT);
        __syncthreads();
    }

    // ---------------- final retrieval ----------------
    issueFin(0);
    CP_WAIT0();
    const float cfac = 0.42f * 1.8f / (float)CAP;
    for (int k = 0; k < NCOND; k++) {
        __syncthreads();
        if (tid < 128) wsum[tid] = 0.f;

        float acc8[2][8][4];
        #pragma unroll
        for (int i = 0; i < 2; i++)
            #pragma unroll
            for (int j = 0; j < 8; j++)
                #pragma unroll
                for (int q = 0; q < 4; q++) acc8[i][j][q] = 0.f;

        #pragma unroll
        for (int ch = 0; ch < 8; ch++) {
            const int colh = ch * 16 + ((lane >> 4) << 3);
            uint32_t a_h[2][4], a_l[2][4], bfr[8][2];
            #pragma unroll
            for (int mt = 0; mt < 2; mt++) {
                int row = wm * 32 + mt * 16 + (lane & 15);
                ldsm4(a_h[mt], aAh + (uint32_t)(row * LDA + colh) * 2);
                ldsm4(a_l[mt], aAl + (uint32_t)(row * LDA + colh) * 2);
            }
            #pragma unroll
            for (int nt2 = 0; nt2 < 4; nt2++) {
                int row = wn * 64 + nt2 * 16 + (lane & 15);
                uint32_t r[4];
                ldsm4(r, aWh + (uint32_t)(row * LDA + colh) * 2);
                bfr[2 * nt2][0] = r[0]; bfr[2 * nt2][1] = r[2];
                bfr[2 * nt2 + 1][0] = r[1]; bfr[2 * nt2 + 1][1] = r[3];
            }
            #pragma unroll
            for (int mt = 0; mt < 2; mt++)
                #pragma unroll
                for (int nt = 0; nt < 8; nt++) mma_bf16(acc8[mt][nt], a_h[mt], bfr[nt]);
            #pragma unroll
            for (int mt = 0; mt < 2; mt++)
                #pragma unroll
                for (int nt = 0; nt < 8; nt++) mma_bf16(acc8[mt][nt], a_l[mt], bfr[nt]);
            #pragma unroll
            for (int nt2 = 0; nt2 < 4; nt2++) {
                int row = wn * 64 + nt2 * 16 + (lane & 15);
                uint32_t r[4];
                ldsm4(r, aWl + (uint32_t)(row * LDA + colh) * 2);
                bfr[2 * nt2][0] = r[0]; bfr[2 * nt2][1] = r[2];
                bfr[2 * nt2 + 1][0] = r[1]; bfr[2 * nt2 + 1][1] = r[3];
            }
            #pragma unroll
            for (int mt = 0; mt < 2; mt++)
                #pragma unroll
                for (int nt = 0; nt < 8; nt++) mma_bf16(acc8[mt][nt], a_h[mt], bfr[nt]);
        }
        __syncthreads();
        if (k + 1 < NCOND) issueFin(k + 1);

        if (wn >= 2) {
            #pragma unroll
            for (int mt = 0; mt < 2; mt++) {
                const int r1 = wm * 32 + mt * 16 + (lane >> 2);
                float p1 = 0.f, p2 = 0.f;
                #pragma unroll
                for (int nt = 0; nt < 8; nt++) {
                    const int e0 = (wn - 2) * 64 + nt * 8 + ((lane & 3) << 1);
                    float m00 = __bfloat162float(sAh[r1 * LDA + e0]) +
                                __bfloat162float(sAl[r1 * LDA + e0]);
                    float m01 = __bfloat162float(sAh[r1 * LDA + e0 + 1]) +
                                __bfloat162float(sAl[r1 * LDA + e0 + 1]);
                    float m10 = __bfloat162float(sAh[(r1 + 8) * LDA + e0]) +
                                __bfloat162float(sAl[(r1 + 8) * LDA + e0]);
                    float m11 = __bfloat162float(sAh[(r1 + 8) * LDA + e0 + 1]) +
                                __bfloat162float(sAl[(r1 + 8) * LDA + e0 + 1]);
                    p1 += acc8[mt][nt][0] * m00 + acc8[mt][nt][1] * m01;
                    p2 += acc8[mt][nt][2] * m10 + acc8[mt][nt][3] * m11;
                }
                atomicAdd(&wsum[r1], p1);
                atomicAdd(&wsum[r1 + 8], p2);
            }
        }
        __syncthreads();
        if (tid < 128) wsum[tid] = wsum[tid] * cfac + 0.3f * saw[tid];
        __syncthreads();

        if (wn < 2) {
            #pragma unroll
            for (int mt = 0; mt < 2; mt++) {
                const int rl = wm * 32 + mt * 16 + (lane >> 2);
                const float w1 = wsum[rl], w2 = wsum[rl + 8];
                #pragma unroll
                for (int nt = 0; nt < 8; nt++) {
                    const int col = wn * 64 + nt * 8 + ((lane & 3) << 1);
                    float2 bv = *(const float2*)(retB + (size_t)k * FEAT + col);
                    size_t base1 = (size_t)(m0 + rl) * (NCOND * FEAT) + (size_t)k * FEAT + col;
                    size_t base2 = (size_t)(m0 + rl + 8) * (NCOND * FEAT) + (size_t)k * FEAT + col;
                    *(float2*)(out + base1) = make_float2((acc8[mt][nt][0] + bv.x) * w1,
                                                          (acc8[mt][nt][1] + bv.y) * w1);
                    *(float2*)(out + base2) = make_float2((acc8[mt][nt][2] + bv.x) * w2,
                                                          (acc8[mt][nt][3] + bv.y) * w2);
                }
            }
        }
        if (k + 1 < NCOND) CP_WAIT0();
    }
}

// ===========================================================================
extern "C" void kernel_launch(void* const* d_in, const int* in_sizes, int n_in,
                              void* d_out, int out_size) {
    const float* sup  = (const float*)d_in[0];
    const float* anom = (const float*)d_in[1];
    const float* ind  = (const float*)d_in[2];
    const float* ipW1 = (const float*)d_in[3];
    const float* ipb1 = (const float*)d_in[4];
    const float* ipW2 = (const float*)d_in[5];
    const float* ipb2 = (const float*)d_in[6];
    const float* consW = (const float*)d_in[7];
    const float* consB = (const float*)d_in[8];
    const float* refp = (const float*)d_in[9];
    const float* objp = (const float*)d_in[10];
    const float* retW = (const float*)d_in[11];
    const float* retB = (const float*)d_in[12];
    float* out = (float*)d_out;

    __nv_bfloat16 *Wh1, *Wl1, *Wh2, *Wl2, *WhC, *WlC, *h1h, *h1l, *WfH, *WfL;
    float *aw;
    cudaGetSymbolAddress((void**)&Wh1, g_Wh1);
    cudaGetSymbolAddress((void**)&Wl1, g_Wl1);
    cudaGetSymbolAddress((void**)&Wh2, g_Wh2);
    cudaGetSymbolAddress((void**)&Wl2, g_Wl2);
    cudaGetSymbolAddress((void**)&WhC, g_WhC);
    cudaGetSymbolAddress((void**)&WlC, g_WlC);
    cudaGetSymbolAddress((void**)&h1h, g_h1h);
    cudaGetSymbolAddress((void**)&h1l, g_h1l);
    cudaGetSymbolAddress((void**)&WfH, g_WfinH);
    cudaGetSymbolAddress((void**)&WfL, g_WfinL);
    cudaGetSymbolAddress((void**)&aw, g_aw);

    cudaFuncSetAttribute(gemm1_v2, cudaFuncAttributeMaxDynamicSharedMemorySize, G1_SMEM);
    cudaFuncSetAttribute(fused_tail, cudaFuncAttributeMaxDynamicSharedMemorySize, TAIL_SMEM);

    // preps (independent)
    aw_kernel<<<BB * 32 / 256, 256>>>(anom, aw);
    mkfin_kernel<<<NCOND, 256>>>(refp, objp, WfH, WfL);
    tsplit_kernel<<<dim3(D_IN / 32, H1 / 32, 1), dim3(32, 8)>>>(ipW1, Wh1, Wl1, D_IN, H1, H1 * D_IN);
    tsplit_kernel<<<dim3(H1 / 32, FEAT / 32, 1), dim3(32, 8)>>>(ipW2, Wh2, Wl2, H1, FEAT, FEAT * H1);
    tsplit_kernel<<<dim3(FEAT / 32, FEAT / 32, DEPTH), dim3(32, 8)>>>(consW, WhC, WlC, FEAT, FEAT, FEAT * FEAT);
    tsplit_kernel<<<dim3(FEAT / 32, FEAT / 32, NCOND), dim3(32, 8)>>>(retW, WfH, WfL, FEAT, FEAT, 256 * FEAT);

    // GEMM1 (pipelined HMMA)
    gemm1_v2<<<BB / 128, 512, G1_SMEM>>>(sup, anom, ind, Wh1, Wl1, ipb1, h1h, h1l);

    // fused tail
    fused_tail<<<BB / 128, 512, TAIL_SMEM>>>(
        h1h, h1l, Wh2, Wl2, ipb2, WhC, WlC, consB, WfH, WfL, retB, aw, out);
}